// round 1
// baseline (speedup 1.0000x reference)
#include <cuda_runtime.h>
#include <math.h>

// ---------------- problem constants ----------------
#define Bn   16
#define Nn   3136        // 56*56
#define Cn   512
#define NH   8
#define HD   64
#define Fn   128         // 2*HD
#define Mrows (Bn*Nn)    // 50176
#define HW   56

// ---------------- scratch (device globals; no allocs allowed) --------------
__device__ __align__(16) float d_qg[Mrows * 1024];          // [b,n, q(512)|g(512)]
__device__ __align__(16) float d_kv[Mrows * 1024];          // [b,n, k(512)|v(512)]
__device__ __align__(16) float d_qf[Bn*NH*Nn*Fn];           // q_sim  [bh,n,128]
__device__ __align__(16) float d_kf[Bn*NH*Nn*Fn];           // kf     [bh,n,128]
__device__ __align__(16) float d_km[Bn*NH*Fn];              // mean over n
__device__ __align__(16) float d_kvm[Bn*NH*Fn*64];          // [bh,d(128),e(64)] e<32:v1 branch, e>=32:v2 branch
__device__ __align__(16) float d_z [Bn*NH*Nn*2];            // z_sim, z_opp
__device__ __align__(16) float d_t [Mrows * Cn];            // (xo + vd) * g

// =====================================================================
// GEMM: C[M,Nc] = A[M,K] @ B[K,Nc] (+ bias)   row-major everywhere.
// 128x128 block tile, BK=16, 256 threads, 8x8 per thread (4+4 split frags).
// =====================================================================
#define BM 128
#define BN 128
#define BK 16

__global__ __launch_bounds__(256, 2)
void gemm_rrr(const float* __restrict__ A, const float* __restrict__ Bm,
              const float* __restrict__ bias, float* __restrict__ Cm,
              int M, int K, int Nc)
{
    __shared__ float As[BK][BM + 4];
    __shared__ float Bs[BK][BN];

    const int tid = threadIdx.x;
    const int bm = blockIdx.y * BM;
    const int bn = blockIdx.x * BN;
    const int tx = tid & 15;          // col group
    const int ty = tid >> 4;          // row group
    const int ar = tid >> 1;          // A load: row in tile
    const int ac = (tid & 1) * 8;     // A load: col in tile
    const int br = tid >> 4;          // B load: row in tile
    const int bc = (tid & 15) * 8;    // B load: col in tile

    float acc[8][8];
#pragma unroll
    for (int i = 0; i < 8; i++)
#pragma unroll
        for (int j = 0; j < 8; j++) acc[i][j] = 0.f;

    for (int k0 = 0; k0 < K; k0 += BK) {
        const float* ap = &A[(size_t)(bm + ar) * K + k0 + ac];
        float4 a0 = *(const float4*)(ap);
        float4 a1 = *(const float4*)(ap + 4);
        const float* bp = &Bm[(size_t)(k0 + br) * Nc + bn + bc];
        float4 b0 = *(const float4*)(bp);
        float4 b1 = *(const float4*)(bp + 4);

        As[ac + 0][ar] = a0.x; As[ac + 1][ar] = a0.y;
        As[ac + 2][ar] = a0.z; As[ac + 3][ar] = a0.w;
        As[ac + 4][ar] = a1.x; As[ac + 5][ar] = a1.y;
        As[ac + 6][ar] = a1.z; As[ac + 7][ar] = a1.w;
        *(float4*)&Bs[br][bc]     = b0;
        *(float4*)&Bs[br][bc + 4] = b1;
        __syncthreads();

#pragma unroll
        for (int kk = 0; kk < BK; kk++) {
            float av[8], bv[8];
            float4 t;
            t = *(const float4*)&As[kk][ty * 4];        av[0]=t.x; av[1]=t.y; av[2]=t.z; av[3]=t.w;
            t = *(const float4*)&As[kk][64 + ty * 4];   av[4]=t.x; av[5]=t.y; av[6]=t.z; av[7]=t.w;
            t = *(const float4*)&Bs[kk][tx * 4];        bv[0]=t.x; bv[1]=t.y; bv[2]=t.z; bv[3]=t.w;
            t = *(const float4*)&Bs[kk][64 + tx * 4];   bv[4]=t.x; bv[5]=t.y; bv[6]=t.z; bv[7]=t.w;
#pragma unroll
            for (int i = 0; i < 8; i++)
#pragma unroll
                for (int j = 0; j < 8; j++)
                    acc[i][j] = fmaf(av[i], bv[j], acc[i][j]);
        }
        __syncthreads();
    }

#pragma unroll
    for (int i = 0; i < 8; i++) {
        int row = bm + ((i < 4) ? (ty * 4 + i) : (64 + ty * 4 + i - 4));
#pragma unroll
        for (int jh = 0; jh < 2; jh++) {
            int col = bn + ((jh == 0) ? (tx * 4) : (64 + tx * 4));
            float4 o;
            o.x = acc[i][jh * 4 + 0]; o.y = acc[i][jh * 4 + 1];
            o.z = acc[i][jh * 4 + 2]; o.w = acc[i][jh * 4 + 3];
            if (bias) {
                o.x += bias[col + 0]; o.y += bias[col + 1];
                o.z += bias[col + 2]; o.w += bias[col + 3];
            }
            *(float4*)&Cm[(size_t)row * Nc + col] = o;
        }
    }
}

// =====================================================================
// Feature kernel: per (b,n,c): scale, pos_enc, pow-relu features.
// grid = Mrows blocks, 512 threads (c).
// =====================================================================
__global__ void features_kernel(const float* __restrict__ pos_enc,
                                const float* __restrict__ scale_p,
                                const float* __restrict__ power_p)
{
    int bn_ = blockIdx.x;              // b*Nn + n
    int c   = threadIdx.x;             // 0..511
    int h   = c >> 6;
    int d   = c & 63;
    int n   = bn_ % Nn;
    int b   = bn_ / Nn;

    float qv = d_qg[(size_t)bn_ * 1024 + c];
    float kvv = d_kv[(size_t)bn_ * 1024 + c] + pos_enc[n * Cn + c];

    float sc = log1pf(expf(scale_p[c]));       // softplus
    qv /= sc;
    kvv /= sc;

    // power_p flattened [1,8,1,64] -> index h*64+d == c
    float pw = 1.f + 4.f / (1.f + expf(-power_p[c]));

    float qp = (qv  > 0.f) ? powf(qv,  pw) : 0.f;
    float qn = (qv  < 0.f) ? powf(-qv, pw) : 0.f;
    float kp = (kvv > 0.f) ? powf(kvv, pw) : 0.f;
    float kn = (kvv < 0.f) ? powf(-kvv, pw) : 0.f;

    size_t fbase = ((size_t)(b * NH + h) * Nn + n) * Fn;
    d_qf[fbase + d]      = qp;
    d_qf[fbase + 64 + d] = qn;
    d_kf[fbase + d]      = kp;
    d_kf[fbase + 64 + d] = kn;
}

// =====================================================================
// zero km + kvm accumulators
// =====================================================================
__global__ void zero_aux_kernel()
{
    int i = blockIdx.x * blockDim.x + threadIdx.x;
    int stride = gridDim.x * blockDim.x;
    if (i < Bn * NH * Fn) d_km[i] = 0.f;
    for (int j = i; j < Bn * NH * Fn * 64; j += stride) d_kvm[j] = 0.f;
}

// =====================================================================
// km partial-sum: grid (128 bh, 8 segs), 128 threads (f)
// =====================================================================
__global__ void km_kernel()
{
    int bh  = blockIdx.x;
    int seg = blockIdx.y;
    int f   = threadIdx.x;
    int n0 = seg * (Nn / 8);
    float s = 0.f;
    const float* src = &d_kf[((size_t)bh * Nn + n0) * Fn + f];
    for (int n = 0; n < Nn / 8; n++) s += src[(size_t)n * Fn];
    atomicAdd(&d_km[bh * Fn + f], s * (1.f / (float)Nn));
}

// =====================================================================
// z kernel: one warp per (bh, n). 8 warps/block, same bh within block.
// =====================================================================
__global__ void z_kernel()
{
    __shared__ float km_s[Fn];
    int warp = threadIdx.x >> 5;
    int lane = threadIdx.x & 31;
    long long wg0 = (long long)blockIdx.x * 8;
    int bh = (int)(wg0 / Nn);
    if (threadIdx.x < Fn) km_s[threadIdx.x] = d_km[bh * Fn + threadIdx.x];
    __syncthreads();

    long long wg = wg0 + warp;
    const float* q = &d_qf[(size_t)wg * Fn];
    float s1 = 0.f, s2 = 0.f;
#pragma unroll
    for (int j = 0; j < 4; j++) {
        int f = lane + 32 * j;
        float qv = q[f];
        s1 += qv * km_s[f];
        s2 += qv * km_s[f ^ 64];
    }
#pragma unroll
    for (int o = 16; o > 0; o >>= 1) {
        s1 += __shfl_xor_sync(0xffffffffu, s1, o);
        s2 += __shfl_xor_sync(0xffffffffu, s2, o);
    }
    if (lane == 0) {
        d_z[wg * 2 + 0] = 1.f / (s1 + 1e-6f);
        d_z[wg * 2 + 1] = 1.f / (s2 + 1e-6f);
    }
}

// =====================================================================
// kvm: per (bh, seg): (1/n) * kf[n,:128]^T @ v[n, e]  (e<32 -> v1, e>=32 -> v2)
// grid (128, 4), 256 threads: thread = (d = tid>>1, half = tid&1), 32 accs.
// =====================================================================
__global__ __launch_bounds__(256)
void kvm_kernel()
{
    __shared__ float kfs[16][Fn];
    __shared__ float vs[16][64];
    int bh = blockIdx.x;
    int b = bh >> 3, h = bh & 7;
    int seg = blockIdx.y;
    int tid = threadIdx.x;
    int dd = tid >> 1;
    int ebase = (tid & 1) * 32;

    float acc[32];
#pragma unroll
    for (int j = 0; j < 32; j++) acc[j] = 0.f;

    int nstart = seg * (Nn / 4);
    for (int n0 = nstart; n0 < nstart + Nn / 4; n0 += 16) {
        {   // kf tile: 16x128
            int idx = tid * 8; int r = idx >> 7; int f = idx & 127;
            const float* src = &d_kf[((size_t)bh * Nn + n0 + r) * Fn + f];
            *(float4*)&kfs[r][f]     = *(const float4*)(src);
            *(float4*)&kfs[r][f + 4] = *(const float4*)(src + 4);
        }
        {   // v tile: 16x64  (v = second half of kv at head h)
            int idx = tid * 4; int r = idx >> 6; int e = idx & 63;
            const float* src = &d_kv[((size_t)(b * Nn) + n0 + r) * 1024 + 512 + h * 64 + e];
            *(float4*)&vs[r][e] = *(const float4*)src;
        }
        __syncthreads();
#pragma unroll
        for (int nn = 0; nn < 16; nn++) {
            float a = kfs[nn][dd];
#pragma unroll
            for (int j = 0; j < 32; j++)
                acc[j] = fmaf(a, vs[nn][ebase + j], acc[j]);
        }
        __syncthreads();
    }
    const float inv_n = 1.f / (float)Nn;
    float* dst = &d_kvm[(size_t)bh * (Fn * 64) + dd * 64 + ebase];
#pragma unroll
    for (int j = 0; j < 32; j++) atomicAdd(&dst[j], acc[j] * inv_n);
}

// =====================================================================
// attention output: x[e] = z * sum_d qf[d (^64 for opp)] * kvm[d][e]
// grid (128 bh, 28 chunks of 112 n), 256 threads.
// writes xo into d_t.
// =====================================================================
__global__ __launch_bounds__(256)
void attn_out_kernel()
{
    __shared__ float kvm_s[Fn * 64];     // 32 KB
    __shared__ float qs[4][Fn];
    int bh = blockIdx.x;
    int b = bh >> 3, h = bh & 7;
    int tid = threadIdx.x;

    {   // load kvm for this bh
        const float* src = &d_kvm[(size_t)bh * (Fn * 64)];
#pragma unroll
        for (int i = 0; i < 8; i++) {
            int idx = (i * 256 + tid) * 4;
            *(float4*)&kvm_s[idx] = *(const float4*)&src[idx];
        }
    }
    __syncthreads();

    int e = tid & 63;
    int nsub = tid >> 6;
    int o1 = (e < 32) ? 0 : 64;
    int o2 = o1 ^ 64;
    int zi = (e < 32) ? 0 : 1;

    int nbase0 = blockIdx.y * 112;
    for (int it = 0; it < 28; it++) {
        int nbase = nbase0 + it * 4;
        // stage 4 q rows
#pragma unroll
        for (int i = 0; i < 2; i++) {
            int idx = i * 256 + tid;
            int nn = idx >> 7, f = idx & 127;
            qs[nn][f] = d_qf[((size_t)bh * Nn + nbase + nn) * Fn + f];
        }
        __syncthreads();

        int n = nbase + nsub;
        float acc = 0.f;
#pragma unroll
        for (int dlo = 0; dlo < 64; dlo++)
            acc = fmaf(qs[nsub][o1 + dlo], kvm_s[dlo * 64 + e], acc);
#pragma unroll
        for (int dlo = 0; dlo < 64; dlo++)
            acc = fmaf(qs[nsub][o2 + dlo], kvm_s[(64 + dlo) * 64 + e], acc);

        float zv = d_z[((size_t)bh * Nn + n) * 2 + zi];
        d_t[((size_t)(b * Nn) + n) * Cn + h * 64 + e] = acc * zv;
        __syncthreads();
    }
}

// =====================================================================
// depthwise 5x5 conv on v + gate:  t = (t + conv(v) + bias) * g
// grid (56 y, 16 b), 512 threads (c).
// =====================================================================
__global__ __launch_bounds__(512)
void conv_gate_kernel(const float* __restrict__ dwc_w,
                      const float* __restrict__ dwc_b)
{
    __shared__ float ws[64 * 25];
    __shared__ float bs[64];
    int y = blockIdx.x;
    int b = blockIdx.y;
    int c = threadIdx.x;
    int d = c & 63;
    for (int i = c; i < 64 * 25; i += 512) ws[i] = dwc_w[i];
    if (c < 64) bs[c] = dwc_b[c];
    __syncthreads();

    for (int x = 0; x < HW; x++) {
        float acc = bs[d];
#pragma unroll
        for (int dy = 0; dy < 5; dy++) {
            int yy = y + dy - 2;
            if ((unsigned)yy >= HW) continue;
#pragma unroll
            for (int dx = 0; dx < 5; dx++) {
                int xx = x + dx - 2;
                if ((unsigned)xx >= HW) continue;
                float vv = d_kv[((size_t)(b * Nn) + yy * HW + xx) * 1024 + 512 + c];
                acc = fmaf(vv, ws[d * 25 + dy * 5 + dx], acc);
            }
        }
        size_t i1 = (size_t)(b * Nn) + y * HW + x;
        float g = d_qg[i1 * 1024 + 512 + c];
        d_t[i1 * Cn + c] = (d_t[i1 * Cn + c] + acc) * g;
    }
}

// =====================================================================
// launch
// =====================================================================
extern "C" void kernel_launch(void* const* d_in, const int* in_sizes, int n_in,
                              void* d_out, int out_size)
{
    const float* x       = (const float*)d_in[0];
    const float* qg_w    = (const float*)d_in[1];
    const float* kv_w    = (const float*)d_in[2];
    const float* proj_w  = (const float*)d_in[3];
    const float* proj_b  = (const float*)d_in[4];
    const float* pos_enc = (const float*)d_in[5];
    const float* scale_p = (const float*)d_in[6];
    const float* power_p = (const float*)d_in[7];
    const float* dwc_w   = (const float*)d_in[8];
    const float* dwc_b   = (const float*)d_in[9];
    float* out = (float*)d_out;

    float *p_qg, *p_kv, *p_t;
    cudaGetSymbolAddress((void**)&p_qg, d_qg);
    cudaGetSymbolAddress((void**)&p_kv, d_kv);
    cudaGetSymbolAddress((void**)&p_t,  d_t);

    // 1. qg = x @ qg_w ; kv = x @ kv_w
    dim3 g1(1024 / BN, Mrows / BM);
    gemm_rrr<<<g1, 256>>>(x, qg_w, nullptr, p_qg, Mrows, Cn, 1024);
    gemm_rrr<<<g1, 256>>>(x, kv_w, nullptr, p_kv, Mrows, Cn, 1024);

    // 2. zero accumulators (before feature/km/kvm use them)
    zero_aux_kernel<<<1024, 256>>>();

    // 3. features
    features_kernel<<<Mrows, 512>>>(pos_enc, scale_p, power_p);

    // 4. km = mean_n kf
    km_kernel<<<dim3(Bn * NH, 8), Fn>>>();

    // 5. z
    z_kernel<<<(Bn * NH * Nn) / 8, 256>>>();

    // 6. kvm = (1/n) kf^T @ [v1 | v2]
    kvm_kernel<<<dim3(Bn * NH, 4), 256>>>();

    // 7. attention output -> d_t
    attn_out_kernel<<<dim3(Bn * NH, Nn / 112), 256>>>();

    // 8. depthwise conv + gate (in-place on d_t)
    conv_gate_kernel<<<dim3(HW, Bn), 512>>>(dwc_w, dwc_b);

    // 9. out = t @ proj_w + proj_b
    dim3 g3(Cn / BN, Mrows / BM);
    gemm_rrr<<<g3, 256>>>(p_t, proj_w, proj_b, out, Mrows, Cn, Cn);
}

// round 4
// speedup vs baseline: 1.7301x; 1.7301x over previous
#include <cuda_runtime.h>
#include <math.h>
#include <stdint.h>

// ---------------- problem constants ----------------
#define Bn   16
#define Nn   3136        // 56*56
#define Cn   512
#define NH   8
#define HD   64
#define Fn   128         // 2*HD
#define Mrows (Bn*Nn)    // 50176
#define HW   56

// ---------------- scratch (device globals; no allocs allowed) --------------
__device__ __align__(16) float d_qg[Mrows * 1024];          // [b,n, q(512)|g(512)]
__device__ __align__(16) float d_kv[Mrows * 1024];          // [b,n, k(512)|v(512)]
__device__ __align__(16) float d_qf[Bn*NH*Nn*Fn];           // q_sim  [bh,n,128]
__device__ __align__(16) float d_kf[Bn*NH*Nn*Fn];           // kf     [bh,n,128]
__device__ __align__(16) float d_km[Bn*NH*Fn];              // mean over n
__device__ __align__(16) float d_kvm[Bn*NH*Fn*64];          // [bh,d(128),e(64)]
__device__ __align__(16) float d_z [Bn*NH*Nn*2];            // z_sim, z_opp
__device__ __align__(16) float d_t [Mrows * Cn];            // (xo + vd) * g
__device__ __align__(16) float d_wt1[1024 * 512];           // qg_w^T  (tf32-rounded)
__device__ __align__(16) float d_wt2[1024 * 512];           // kv_w^T
__device__ __align__(16) float d_wt3[512 * 512];            // proj_w^T
__device__ __align__(16) float d_scinv[Cn];                 // 1/softplus(scale_p)
__device__ __align__(16) float d_pw[Cn];                    // 1+4*sigmoid(power_p)

// =====================================================================
// helpers (all baseline sm_80-level PTX; no 'a'-gated features)
// =====================================================================
__device__ __forceinline__ uint32_t smem_u32(const void* p) {
    uint32_t a;
    asm("{ .reg .u64 t; cvta.to.shared.u64 t, %1; cvt.u32.u64 %0, t; }"
        : "=r"(a) : "l"(p));
    return a;
}

__device__ __forceinline__ float to_tf32(float x) {
    float r;
    asm("cvt.rna.tf32.f32 %0, %1;" : "=f"(r) : "f"(x));
    return r;
}

__device__ __forceinline__ uint32_t to_tf32_u(float x) {
    uint32_t r;
    asm("cvt.rna.tf32.f32 %0, %1;" : "=r"(r) : "f"(x));
    return r;
}

__device__ __forceinline__ void cp_async16(uint32_t saddr, const void* gaddr) {
    asm volatile("cp.async.ca.shared.global [%0], [%1], 16;"
                 :: "r"(saddr), "l"(gaddr) : "memory");
}
#define CP_COMMIT() asm volatile("cp.async.commit_group;" ::: "memory")
#define CP_WAIT(N)  asm volatile("cp.async.wait_group %0;" :: "n"(N) : "memory")

__device__ __forceinline__ void mma_tf32_16_8_8(float* c, const uint32_t* a,
                                                const uint32_t* b) {
    asm volatile(
        "mma.sync.aligned.m16n8k8.row.col.f32.tf32.tf32.f32 "
        "{%0,%1,%2,%3}, {%4,%5,%6,%7}, {%8,%9}, {%0,%1,%2,%3};"
        : "+f"(c[0]), "+f"(c[1]), "+f"(c[2]), "+f"(c[3])
        : "r"(a[0]), "r"(a[1]), "r"(a[2]), "r"(a[3]), "r"(b[0]), "r"(b[1]));
}

// =====================================================================
// tensor-core tf32 GEMM:  C[M,Nc] = A[M,512] @ Bt[Nc,512]^T  (+bias)
// 128x128 CTA tile, BK=32, 256 thr, warp tile 64x32 (2x4 warp grid),
// cp.async double buffer, stride-36 padded smem (conflict-free frags).
// =====================================================================
#define GM 128
#define GN 128
#define GK 32
#define SST 36                          // smem row stride (floats)
#define ABUF (128 * SST)                // floats per buffer
#define GEMM_SMEM (4 * ABUF * 4)        // 73728 bytes

__global__ __launch_bounds__(256, 2)
void gemm_mma(const float* __restrict__ A, const float* __restrict__ Bt,
              const float* __restrict__ bias, float* __restrict__ Cm, int Nc)
{
    extern __shared__ float sm[];
    float* smA[2] = { sm,            sm + ABUF };
    float* smB[2] = { sm + 2 * ABUF, sm + 3 * ABUF };
    const uint32_t suA[2] = { smem_u32(smA[0]), smem_u32(smA[1]) };
    const uint32_t suB[2] = { smem_u32(smB[0]), smem_u32(smB[1]) };

    const int tid = threadIdx.x;
    const int bn0 = blockIdx.x * GN;
    const int bm0 = blockIdx.y * GM;
    const int wid = tid >> 5, lane = tid & 31;
    const int wm = (wid & 1) * 64;       // warp M offset
    const int wn = (wid >> 1) * 32;      // warp N offset
    const int lr = lane >> 2, lc = lane & 3;

    float c[4][4][4];
#pragma unroll
    for (int mt = 0; mt < 4; mt++)
#pragma unroll
        for (int nt = 0; nt < 4; nt++)
#pragma unroll
            for (int j = 0; j < 4; j++) c[mt][nt][j] = 0.f;

    const int r_ld  = tid >> 3;          // 0..31? no: tid>>3 with i offsets below
    const int c4_ld = tid & 7;

    // prefetch tile 0
    {
#pragma unroll
        for (int i = 0; i < 4; i++) {
            int idx = tid + i * 256;
            int r = idx >> 3, c4 = idx & 7;
            cp_async16(suA[0] + (r * SST + c4 * 4) * 4,
                       &A[(size_t)(bm0 + r) * 512 + c4 * 4]);
            cp_async16(suB[0] + (r * SST + c4 * 4) * 4,
                       &Bt[(size_t)(bn0 + r) * 512 + c4 * 4]);
        }
        CP_COMMIT();
    }

    const int NT = 512 / GK;             // 16
    int buf = 0;
    for (int t = 0; t < NT; t++) {
        if (t + 1 < NT) {
            int nb = buf ^ 1;
            int k0 = (t + 1) * GK;
#pragma unroll
            for (int i = 0; i < 4; i++) {
                int idx = tid + i * 256;
                int r = idx >> 3, c4 = idx & 7;
                cp_async16(suA[nb] + (r * SST + c4 * 4) * 4,
                           &A[(size_t)(bm0 + r) * 512 + k0 + c4 * 4]);
                cp_async16(suB[nb] + (r * SST + c4 * 4) * 4,
                           &Bt[(size_t)(bn0 + r) * 512 + k0 + c4 * 4]);
            }
            CP_COMMIT();
            CP_WAIT(1);
        } else {
            CP_WAIT(0);
        }
        __syncthreads();

        const float* As = smA[buf];
        const float* Bs = smB[buf];
#pragma unroll
        for (int kk = 0; kk < 4; kk++) {
            const int k0 = kk * 8;
            uint32_t a[4][4], b[4][2];
#pragma unroll
            for (int mt = 0; mt < 4; mt++) {
                int r = wm + mt * 16 + lr;
                a[mt][0] = to_tf32_u(As[r * SST + k0 + lc]);
                a[mt][1] = to_tf32_u(As[(r + 8) * SST + k0 + lc]);
                a[mt][2] = to_tf32_u(As[r * SST + k0 + lc + 4]);
                a[mt][3] = to_tf32_u(As[(r + 8) * SST + k0 + lc + 4]);
            }
#pragma unroll
            for (int nt = 0; nt < 4; nt++) {
                int n = wn + nt * 8 + lr;
                b[nt][0] = __float_as_uint(Bs[n * SST + k0 + lc]);
                b[nt][1] = __float_as_uint(Bs[n * SST + k0 + lc + 4]);
            }
#pragma unroll
            for (int mt = 0; mt < 4; mt++)
#pragma unroll
                for (int nt = 0; nt < 4; nt++)
                    mma_tf32_16_8_8(c[mt][nt], a[mt], b[nt]);
        }
        __syncthreads();
        buf ^= 1;
    }

    // epilogue: c0,c1 -> (row, col..col+1); c2,c3 -> (row+8, ...)
#pragma unroll
    for (int mt = 0; mt < 4; mt++) {
        int row = bm0 + wm + mt * 16 + lr;
#pragma unroll
        for (int nt = 0; nt < 4; nt++) {
            int col = bn0 + wn + nt * 8 + lc * 2;
            float2 v0 = make_float2(c[mt][nt][0], c[mt][nt][1]);
            float2 v1 = make_float2(c[mt][nt][2], c[mt][nt][3]);
            if (bias) {
                float b0 = bias[col], b1 = bias[col + 1];
                v0.x += b0; v0.y += b1;
                v1.x += b0; v1.y += b1;
            }
            *(float2*)&Cm[(size_t)row * Nc + col] = v0;
            *(float2*)&Cm[(size_t)(row + 8) * Nc + col] = v1;
        }
    }
}

// =====================================================================
// weight transpose + tf32 rounding:  Wt[n][k] = tf32(W[k][n]),  K=512
// =====================================================================
__global__ void transpose_w(const float* __restrict__ W, float* __restrict__ Wt, int Nc)
{
    __shared__ float t[32][33];
    int bx = blockIdx.x * 32;   // n
    int by = blockIdx.y * 32;   // k
    int x = threadIdx.x, y = threadIdx.y;
#pragma unroll
    for (int j = 0; j < 32; j += 8)
        t[y + j][x] = W[(size_t)(by + y + j) * Nc + bx + x];
    __syncthreads();
#pragma unroll
    for (int j = 0; j < 32; j += 8)
        Wt[(size_t)(bx + y + j) * 512 + by + x] = to_tf32(t[x][y + j]);
}

// =====================================================================
// per-channel params: 1/softplus(scale), 1+4*sigmoid(power)
// =====================================================================
__global__ void prep_params(const float* __restrict__ scale_p,
                            const float* __restrict__ power_p)
{
    int c = threadIdx.x;
    d_scinv[c] = 1.f / log1pf(expf(scale_p[c]));
    d_pw[c] = 1.f + 4.f / (1.f + expf(-power_p[c]));
}

// =====================================================================
// features: scale + pow-relu, branch-free fast pow
// =====================================================================
__global__ void features_kernel(const float* __restrict__ pos_enc)
{
    int bn_ = blockIdx.x;
    int c   = threadIdx.x;
    int h   = c >> 6;
    int d   = c & 63;
    int n   = bn_ % Nn;
    int b   = bn_ / Nn;

    float scinv = d_scinv[c];
    float pw    = d_pw[c];

    float qv  = d_qg[(size_t)bn_ * 1024 + c] * scinv;
    float kvv = (d_kv[(size_t)bn_ * 1024 + c] + pos_enc[n * Cn + c]) * scinv;

    // |x|==0 -> log2=-inf -> exp2(-inf)=0, so no special-casing needed
    float qa = exp2f(pw * __log2f(fabsf(qv)));
    float ka = exp2f(pw * __log2f(fabsf(kvv)));
    float qp = (qv  > 0.f) ? qa : 0.f;
    float qn = (qv  < 0.f) ? qa : 0.f;
    float kp = (kvv > 0.f) ? ka : 0.f;
    float kn = (kvv < 0.f) ? ka : 0.f;

    size_t fbase = ((size_t)(b * NH + h) * Nn + n) * Fn;
    d_qf[fbase + d]      = qp;
    d_qf[fbase + 64 + d] = qn;
    d_kf[fbase + d]      = kp;
    d_kf[fbase + 64 + d] = kn;
}

// =====================================================================
// zero km + kvm accumulators
// =====================================================================
__global__ void zero_aux_kernel()
{
    int i = blockIdx.x * blockDim.x + threadIdx.x;
    int stride = gridDim.x * blockDim.x;
    if (i < Bn * NH * Fn) d_km[i] = 0.f;
    for (int j = i; j < Bn * NH * Fn * 64; j += stride) d_kvm[j] = 0.f;
}

// =====================================================================
// km partial-sum
// =====================================================================
__global__ void km_kernel()
{
    int bh  = blockIdx.x;
    int seg = blockIdx.y;
    int f   = threadIdx.x;
    int n0 = seg * (Nn / 8);
    float s = 0.f;
    const float* src = &d_kf[((size_t)bh * Nn + n0) * Fn + f];
    for (int n = 0; n < Nn / 8; n++) s += src[(size_t)n * Fn];
    atomicAdd(&d_km[bh * Fn + f], s * (1.f / (float)Nn));
}

// =====================================================================
// z kernel
// =====================================================================
__global__ void z_kernel()
{
    __shared__ float km_s[Fn];
    int warp = threadIdx.x >> 5;
    int lane = threadIdx.x & 31;
    long long wg0 = (long long)blockIdx.x * 8;
    int bh = (int)(wg0 / Nn);
    if (threadIdx.x < Fn) km_s[threadIdx.x] = d_km[bh * Fn + threadIdx.x];
    __syncthreads();

    long long wg = wg0 + warp;
    const float* q = &d_qf[(size_t)wg * Fn];
    float s1 = 0.f, s2 = 0.f;
#pragma unroll
    for (int j = 0; j < 4; j++) {
        int f = lane + 32 * j;
        float qv = q[f];
        s1 += qv * km_s[f];
        s2 += qv * km_s[f ^ 64];
    }
#pragma unroll
    for (int o = 16; o > 0; o >>= 1) {
        s1 += __shfl_xor_sync(0xffffffffu, s1, o);
        s2 += __shfl_xor_sync(0xffffffffu, s2, o);
    }
    if (lane == 0) {
        d_z[wg * 2 + 0] = 1.f / (s1 + 1e-6f);
        d_z[wg * 2 + 1] = 1.f / (s2 + 1e-6f);
    }
}

// =====================================================================
// kvm
// =====================================================================
__global__ __launch_bounds__(256)
void kvm_kernel()
{
    __shared__ float kfs[16][Fn];
    __shared__ float vs[16][64];
    int bh = blockIdx.x;
    int b = bh >> 3, h = bh & 7;
    int seg = blockIdx.y;
    int tid = threadIdx.x;
    int dd = tid >> 1;
    int ebase = (tid & 1) * 32;

    float acc[32];
#pragma unroll
    for (int j = 0; j < 32; j++) acc[j] = 0.f;

    int nstart = seg * (Nn / 4);
    for (int n0 = nstart; n0 < nstart + Nn / 4; n0 += 16) {
        {
            int idx = tid * 8; int r = idx >> 7; int f = idx & 127;
            const float* src = &d_kf[((size_t)bh * Nn + n0 + r) * Fn + f];
            *(float4*)&kfs[r][f]     = *(const float4*)(src);
            *(float4*)&kfs[r][f + 4] = *(const float4*)(src + 4);
        }
        {
            int idx = tid * 4; int r = idx >> 6; int e = idx & 63;
            const float* src = &d_kv[((size_t)(b * Nn) + n0 + r) * 1024 + 512 + h * 64 + e];
            *(float4*)&vs[r][e] = *(const float4*)src;
        }
        __syncthreads();
#pragma unroll
        for (int nn = 0; nn < 16; nn++) {
            float a = kfs[nn][dd];
#pragma unroll
            for (int j = 0; j < 32; j++)
                acc[j] = fmaf(a, vs[nn][ebase + j], acc[j]);
        }
        __syncthreads();
    }
    const float inv_n = 1.f / (float)Nn;
    float* dst = &d_kvm[(size_t)bh * (Fn * 64) + dd * 64 + ebase];
#pragma unroll
    for (int j = 0; j < 32; j++) atomicAdd(&dst[j], acc[j] * inv_n);
}

// =====================================================================
// attention output
// =====================================================================
__global__ __launch_bounds__(256)
void attn_out_kernel()
{
    __shared__ float kvm_s[Fn * 64];
    __shared__ float qs[4][Fn];
    int bh = blockIdx.x;
    int b = bh >> 3, h = bh & 7;
    int tid = threadIdx.x;

    {
        const float* src = &d_kvm[(size_t)bh * (Fn * 64)];
#pragma unroll
        for (int i = 0; i < 8; i++) {
            int idx = (i * 256 + tid) * 4;
            *(float4*)&kvm_s[idx] = *(const float4*)&src[idx];
        }
    }
    __syncthreads();

    int e = tid & 63;
    int nsub = tid >> 6;
    int o1 = (e < 32) ? 0 : 64;
    int o2 = o1 ^ 64;
    int zi = (e < 32) ? 0 : 1;

    int nbase0 = blockIdx.y * 112;
    for (int it = 0; it < 28; it++) {
        int nbase = nbase0 + it * 4;
#pragma unroll
        for (int i = 0; i < 2; i++) {
            int idx = i * 256 + tid;
            int nn = idx >> 7, f = idx & 127;
            qs[nn][f] = d_qf[((size_t)bh * Nn + nbase + nn) * Fn + f];
        }
        __syncthreads();

        int n = nbase + nsub;
        float acc = 0.f;
#pragma unroll
        for (int dlo = 0; dlo < 64; dlo++)
            acc = fmaf(qs[nsub][o1 + dlo], kvm_s[dlo * 64 + e], acc);
#pragma unroll
        for (int dlo = 0; dlo < 64; dlo++)
            acc = fmaf(qs[nsub][o2 + dlo], kvm_s[(64 + dlo) * 64 + e], acc);

        float zv = d_z[((size_t)bh * Nn + n) * 2 + zi];
        d_t[((size_t)(b * Nn) + n) * Cn + h * 64 + e] = acc * zv;
        __syncthreads();
    }
}

// =====================================================================
// depthwise 5x5 conv + gate
// =====================================================================
__global__ __launch_bounds__(512)
void conv_gate_kernel(const float* __restrict__ dwc_w,
                      const float* __restrict__ dwc_b)
{
    __shared__ float ws[64 * 25];
    __shared__ float bs[64];
    int y = blockIdx.x;
    int b = blockIdx.y;
    int c = threadIdx.x;
    int d = c & 63;
    for (int i = c; i < 64 * 25; i += 512) ws[i] = dwc_w[i];
    if (c < 64) bs[c] = dwc_b[c];
    __syncthreads();

    for (int x = 0; x < HW; x++) {
        float acc = bs[d];
#pragma unroll
        for (int dy = 0; dy < 5; dy++) {
            int yy = y + dy - 2;
            if ((unsigned)yy >= HW) continue;
#pragma unroll
            for (int dx = 0; dx < 5; dx++) {
                int xx = x + dx - 2;
                if ((unsigned)xx >= HW) continue;
                float vv = d_kv[((size_t)(b * Nn) + yy * HW + xx) * 1024 + 512 + c];
                acc = fmaf(vv, ws[d * 25 + dy * 5 + dx], acc);
            }
        }
        size_t i1 = (size_t)(b * Nn) + y * HW + x;
        float g = d_qg[i1 * 1024 + 512 + c];
        d_t[i1 * Cn + c] = (d_t[i1 * Cn + c] + acc) * g;
    }
}

// =====================================================================
// launch
// =====================================================================
extern "C" void kernel_launch(void* const* d_in, const int* in_sizes, int n_in,
                              void* d_out, int out_size)
{
    const float* x       = (const float*)d_in[0];
    const float* qg_w    = (const float*)d_in[1];
    const float* kv_w    = (const float*)d_in[2];
    const float* proj_w  = (const float*)d_in[3];
    const float* proj_b  = (const float*)d_in[4];
    const float* pos_enc = (const float*)d_in[5];
    const float* scale_p = (const float*)d_in[6];
    const float* power_p = (const float*)d_in[7];
    const float* dwc_w   = (const float*)d_in[8];
    const float* dwc_b   = (const float*)d_in[9];
    float* out = (float*)d_out;

    float *p_qg, *p_kv, *p_t, *p_wt1, *p_wt2, *p_wt3;
    cudaGetSymbolAddress((void**)&p_qg,  d_qg);
    cudaGetSymbolAddress((void**)&p_kv,  d_kv);
    cudaGetSymbolAddress((void**)&p_t,   d_t);
    cudaGetSymbolAddress((void**)&p_wt1, d_wt1);
    cudaGetSymbolAddress((void**)&p_wt2, d_wt2);
    cudaGetSymbolAddress((void**)&p_wt3, d_wt3);

    cudaFuncSetAttribute(gemm_mma, cudaFuncAttributeMaxDynamicSharedMemorySize,
                         GEMM_SMEM);

    dim3 tb(32, 8);
    // 0. weight transposes (tf32-rounded) + per-channel params
    transpose_w<<<dim3(1024 / 32, 512 / 32), tb>>>(qg_w,   p_wt1, 1024);
    transpose_w<<<dim3(1024 / 32, 512 / 32), tb>>>(kv_w,   p_wt2, 1024);
    transpose_w<<<dim3(512 / 32,  512 / 32), tb>>>(proj_w, p_wt3, 512);
    prep_params<<<1, 512>>>(scale_p, power_p);

    // 1. qg = x @ qg_w ; kv = x @ kv_w   (tensor-core tf32 mma.sync)
    gemm_mma<<<dim3(1024 / GN, Mrows / GM), 256, GEMM_SMEM>>>(x, p_wt1, nullptr, p_qg, 1024);
    gemm_mma<<<dim3(1024 / GN, Mrows / GM), 256, GEMM_SMEM>>>(x, p_wt2, nullptr, p_kv, 1024);

    // 2. zero accumulators
    zero_aux_kernel<<<1024, 256>>>();

    // 3. features
    features_kernel<<<Mrows, 512>>>(pos_enc);

    // 4-7. linear-attention pieces
    km_kernel<<<dim3(Bn * NH, 8), Fn>>>();
    z_kernel<<<(Bn * NH * Nn) / 8, 256>>>();
    kvm_kernel<<<dim3(Bn * NH, 4), 256>>>();
    attn_out_kernel<<<dim3(Bn * NH, Nn / 112), 256>>>();

    // 8. depthwise conv + gate
    conv_gate_kernel<<<dim3(HW, Bn), 512>>>(dwc_w, dwc_b);

    // 9. out = t @ proj_w + proj_b   (tensor-core tf32 mma.sync)
    gemm_mma<<<dim3(512 / GN, Mrows / GM), 256, GEMM_SMEM>>>(p_t, p_wt3, proj_b, out, 512);
}

// round 5
// speedup vs baseline: 1.8247x; 1.0547x over previous
#include <cuda_runtime.h>
#include <cuda_bf16.h>
#include <math.h>
#include <stdint.h>

// ---------------- problem constants ----------------
#define Bn   16
#define Nn   3136        // 56*56
#define Cn   512
#define NH   8
#define HD   64
#define Fn   128         // 2*HD
#define Mrows (Bn*Nn)    // 50176
#define HW   56

// ---------------- scratch (device globals; no allocs allowed) --------------
__device__ __align__(16) float d_qg[Mrows * 1024];          // [b,n, q(512)|g(512)]
__device__ __align__(16) float d_kv[Mrows * 1024];          // [b,n, k(512)|v(512)]
__device__ __align__(16) float d_xr[Mrows * 512];           // tf32-rounded x
__device__ __align__(16) __nv_bfloat16 d_qf[Bn*NH*Nn*Fn];   // q_sim  [bh,n,128] bf16
__device__ __align__(16) __nv_bfloat16 d_kf[Bn*NH*Nn*Fn];   // kf     [bh,n,128] bf16
__device__ __align__(16) float d_km[Bn*NH*Fn];              // mean over n
__device__ __align__(16) float d_kvm[Bn*NH*Fn*64];          // [bh,d(128),e(64)]
__device__ __align__(16) float d_z [Bn*NH*Nn*2];            // z_sim, z_opp
__device__ __align__(16) float d_t [Mrows * Cn];            // (xo + vd) * g, tf32-rounded
__device__ __align__(16) float d_wt1[1024 * 512];           // qg_w^T  (tf32-rounded)
__device__ __align__(16) float d_wt2[1024 * 512];           // kv_w^T
__device__ __align__(16) float d_wt3[512 * 512];            // proj_w^T
__device__ __align__(16) float d_scinv[Cn];                 // 1/softplus(scale_p)
__device__ __align__(16) float d_pw[Cn];                    // 1+4*sigmoid(power_p)

// =====================================================================
// helpers (baseline PTX only; no 'a'-gated features)
// =====================================================================
__device__ __forceinline__ uint32_t smem_u32(const void* p) {
    uint32_t a;
    asm("{ .reg .u64 t; cvta.to.shared.u64 t, %1; cvt.u32.u64 %0, t; }"
        : "=r"(a) : "l"(p));
    return a;
}

__device__ __forceinline__ float to_tf32(float x) {
    float r;
    asm("cvt.rna.tf32.f32 %0, %1;" : "=f"(r) : "f"(x));
    return r;
}

__device__ __forceinline__ void cp_async16(uint32_t saddr, const void* gaddr) {
    asm volatile("cp.async.ca.shared.global [%0], [%1], 16;"
                 :: "r"(saddr), "l"(gaddr) : "memory");
}
#define CP_COMMIT() asm volatile("cp.async.commit_group;" ::: "memory")
#define CP_WAIT(N)  asm volatile("cp.async.wait_group %0;" :: "n"(N) : "memory")

__device__ __forceinline__ void mma_tf32_16_8_8(float* c, const uint32_t* a,
                                                const uint32_t* b) {
    asm volatile(
        "mma.sync.aligned.m16n8k8.row.col.f32.tf32.tf32.f32 "
        "{%0,%1,%2,%3}, {%4,%5,%6,%7}, {%8,%9}, {%0,%1,%2,%3};"
        : "+f"(c[0]), "+f"(c[1]), "+f"(c[2]), "+f"(c[3])
        : "r"(a[0]), "r"(a[1]), "r"(a[2]), "r"(a[3]), "r"(b[0]), "r"(b[1]));
}

// =====================================================================
// tensor-core tf32 GEMM:  C[M,Nc] = A[M,512] @ Bt[Nc,512]^T  (+bias)
// A and Bt are ALREADY tf32-rounded. 128x128 CTA, BK=32, 256 thr,
// warp tile 64x32, cp.async double buffer, stride-36 padded smem.
// =====================================================================
#define GM 128
#define GN 128
#define GK 32
#define SST 36
#define ABUF (128 * SST)
#define GEMM_SMEM (4 * ABUF * 4)        // 73728 bytes

__global__ __launch_bounds__(256, 2)
void gemm_mma(const float* __restrict__ A, const float* __restrict__ Bt,
              const float* __restrict__ bias, float* __restrict__ Cm, int Nc)
{
    extern __shared__ float sm[];
    float* smA[2] = { sm,            sm + ABUF };
    float* smB[2] = { sm + 2 * ABUF, sm + 3 * ABUF };
    const uint32_t suA[2] = { smem_u32(smA[0]), smem_u32(smA[1]) };
    const uint32_t suB[2] = { smem_u32(smB[0]), smem_u32(smB[1]) };

    const int tid = threadIdx.x;
    const int bn0 = blockIdx.x * GN;
    const int bm0 = blockIdx.y * GM;
    const int wid = tid >> 5, lane = tid & 31;
    const int wm = (wid & 1) * 64;
    const int wn = (wid >> 1) * 32;
    const int lr = lane >> 2, lc = lane & 3;

    float c[4][4][4];
#pragma unroll
    for (int mt = 0; mt < 4; mt++)
#pragma unroll
        for (int nt = 0; nt < 4; nt++)
#pragma unroll
            for (int j = 0; j < 4; j++) c[mt][nt][j] = 0.f;

    {
#pragma unroll
        for (int i = 0; i < 4; i++) {
            int idx = tid + i * 256;
            int r = idx >> 3, c4 = idx & 7;
            cp_async16(suA[0] + (r * SST + c4 * 4) * 4,
                       &A[(size_t)(bm0 + r) * 512 + c4 * 4]);
            cp_async16(suB[0] + (r * SST + c4 * 4) * 4,
                       &Bt[(size_t)(bn0 + r) * 512 + c4 * 4]);
        }
        CP_COMMIT();
    }

    const int NT = 512 / GK;
    int buf = 0;
    for (int t = 0; t < NT; t++) {
        if (t + 1 < NT) {
            int nb = buf ^ 1;
            int k0 = (t + 1) * GK;
#pragma unroll
            for (int i = 0; i < 4; i++) {
                int idx = tid + i * 256;
                int r = idx >> 3, c4 = idx & 7;
                cp_async16(suA[nb] + (r * SST + c4 * 4) * 4,
                           &A[(size_t)(bm0 + r) * 512 + k0 + c4 * 4]);
                cp_async16(suB[nb] + (r * SST + c4 * 4) * 4,
                           &Bt[(size_t)(bn0 + r) * 512 + k0 + c4 * 4]);
            }
            CP_COMMIT();
            CP_WAIT(1);
        } else {
            CP_WAIT(0);
        }
        __syncthreads();

        const float* As = smA[buf];
        const float* Bs = smB[buf];
#pragma unroll
        for (int kk = 0; kk < 4; kk++) {
            const int k0 = kk * 8;
            uint32_t a[4][4], b[4][2];
#pragma unroll
            for (int mt = 0; mt < 4; mt++) {
                int r = wm + mt * 16 + lr;
                a[mt][0] = __float_as_uint(As[r * SST + k0 + lc]);
                a[mt][1] = __float_as_uint(As[(r + 8) * SST + k0 + lc]);
                a[mt][2] = __float_as_uint(As[r * SST + k0 + lc + 4]);
                a[mt][3] = __float_as_uint(As[(r + 8) * SST + k0 + lc + 4]);
            }
#pragma unroll
            for (int nt = 0; nt < 4; nt++) {
                int n = wn + nt * 8 + lr;
                b[nt][0] = __float_as_uint(Bs[n * SST + k0 + lc]);
                b[nt][1] = __float_as_uint(Bs[n * SST + k0 + lc + 4]);
            }
#pragma unroll
            for (int mt = 0; mt < 4; mt++)
#pragma unroll
                for (int nt = 0; nt < 4; nt++)
                    mma_tf32_16_8_8(c[mt][nt], a[mt], b[nt]);
        }
        __syncthreads();
        buf ^= 1;
    }

#pragma unroll
    for (int mt = 0; mt < 4; mt++) {
        int row = bm0 + wm + mt * 16 + lr;
#pragma unroll
        for (int nt = 0; nt < 4; nt++) {
            int col = bn0 + wn + nt * 8 + lc * 2;
            float2 v0 = make_float2(c[mt][nt][0], c[mt][nt][1]);
            float2 v1 = make_float2(c[mt][nt][2], c[mt][nt][3]);
            if (bias) {
                float b0 = bias[col], b1 = bias[col + 1];
                v0.x += b0; v0.y += b1;
                v1.x += b0; v1.y += b1;
            }
            *(float2*)&Cm[(size_t)row * Nc + col] = v0;
            *(float2*)&Cm[(size_t)(row + 8) * Nc + col] = v1;
        }
    }
}

// =====================================================================
// weight transpose + tf32 rounding
// =====================================================================
__global__ void transpose_w(const float* __restrict__ W, float* __restrict__ Wt, int Nc)
{
    __shared__ float t[32][33];
    int bx = blockIdx.x * 32;   // n
    int by = blockIdx.y * 32;   // k
    int x = threadIdx.x, y = threadIdx.y;
#pragma unroll
    for (int j = 0; j < 32; j += 8)
        t[y + j][x] = W[(size_t)(by + y + j) * Nc + bx + x];
    __syncthreads();
#pragma unroll
    for (int j = 0; j < 32; j += 8)
        Wt[(size_t)(bx + y + j) * 512 + by + x] = to_tf32(t[x][y + j]);
}

// =====================================================================
// round x -> tf32 copy (A operand for gemm1/gemm2)
// =====================================================================
__global__ void round_x(const float* __restrict__ x)
{
    size_t i = ((size_t)blockIdx.x * 256 + threadIdx.x) * 4;
    float4 v = *(const float4*)&x[i];
    v.x = to_tf32(v.x); v.y = to_tf32(v.y);
    v.z = to_tf32(v.z); v.w = to_tf32(v.w);
    *(float4*)&d_xr[i] = v;
}

// =====================================================================
// per-channel params
// =====================================================================
__global__ void prep_params(const float* __restrict__ scale_p,
                            const float* __restrict__ power_p)
{
    int c = threadIdx.x;
    d_scinv[c] = 1.f / log1pf(expf(scale_p[c]));
    d_pw[c] = 1.f + 4.f / (1.f + expf(-power_p[c]));
}

// =====================================================================
// features + fused km: block = 16 consecutive n of one b, 512 thr (c).
// writes bf16 qf/kf; accumulates km in regs, one atomicAdd pair at end.
// =====================================================================
__global__ __launch_bounds__(512)
void features_kernel(const float* __restrict__ pos_enc)
{
    int c   = threadIdx.x;
    int h   = c >> 6;
    int d   = c & 63;
    int bn0 = blockIdx.x * 16;          // 3136 % 16 == 0 -> single b per block
    int b   = bn0 / Nn;
    int n0  = bn0 - b * Nn;

    float scinv = d_scinv[c];
    float pw    = d_pw[c];
    float skp = 0.f, skn = 0.f;

#pragma unroll 4
    for (int i = 0; i < 16; i++) {
        int bn_ = bn0 + i;
        int n   = n0 + i;
        float qv  = d_qg[(size_t)bn_ * 1024 + c] * scinv;
        float kvv = (d_kv[(size_t)bn_ * 1024 + c] + pos_enc[n * Cn + c]) * scinv;

        float qa = exp2f(pw * __log2f(fabsf(qv)));
        float ka = exp2f(pw * __log2f(fabsf(kvv)));
        float qp = (qv  > 0.f) ? qa : 0.f;
        float qn = (qv  < 0.f) ? qa : 0.f;
        float kp = (kvv > 0.f) ? ka : 0.f;
        float kn = (kvv < 0.f) ? ka : 0.f;

        size_t fbase = ((size_t)(b * NH + h) * Nn + n) * Fn;
        d_qf[fbase + d]      = __float2bfloat16_rn(qp);
        d_qf[fbase + 64 + d] = __float2bfloat16_rn(qn);
        d_kf[fbase + d]      = __float2bfloat16_rn(kp);
        d_kf[fbase + 64 + d] = __float2bfloat16_rn(kn);
        skp += kp; skn += kn;
    }
    const float inv_n = 1.f / (float)Nn;
    atomicAdd(&d_km[(b * NH + h) * Fn + d],      skp * inv_n);
    atomicAdd(&d_km[(b * NH + h) * Fn + 64 + d], skn * inv_n);
}

// =====================================================================
// zero km + kvm accumulators
// =====================================================================
__global__ void zero_aux_kernel()
{
    int i = blockIdx.x * blockDim.x + threadIdx.x;
    int stride = gridDim.x * blockDim.x;
    if (i < Bn * NH * Fn) d_km[i] = 0.f;
    for (int j = i; j < Bn * NH * Fn * 64; j += stride) d_kvm[j] = 0.f;
}

// =====================================================================
// z kernel (bf16 qf)
// =====================================================================
__global__ void z_kernel()
{
    __shared__ float km_s[Fn];
    int warp = threadIdx.x >> 5;
    int lane = threadIdx.x & 31;
    long long wg0 = (long long)blockIdx.x * 8;
    int bh = (int)(wg0 / Nn);
    if (threadIdx.x < Fn) km_s[threadIdx.x] = d_km[bh * Fn + threadIdx.x];
    __syncthreads();

    long long wg = wg0 + warp;
    const __nv_bfloat16* q = &d_qf[(size_t)wg * Fn];
    float s1 = 0.f, s2 = 0.f;
#pragma unroll
    for (int j = 0; j < 4; j++) {
        int f = lane + 32 * j;
        float qv = __bfloat162float(q[f]);
        s1 += qv * km_s[f];
        s2 += qv * km_s[f ^ 64];
    }
#pragma unroll
    for (int o = 16; o > 0; o >>= 1) {
        s1 += __shfl_xor_sync(0xffffffffu, s1, o);
        s2 += __shfl_xor_sync(0xffffffffu, s2, o);
    }
    if (lane == 0) {
        d_z[wg * 2 + 0] = 1.f / (s1 + 1e-6f);
        d_z[wg * 2 + 1] = 1.f / (s2 + 1e-6f);
    }
}

// =====================================================================
// kvm (bf16 kf tiles, fp32 smem)
// =====================================================================
__global__ __launch_bounds__(256)
void kvm_kernel()
{
    __shared__ float kfs[16][Fn];
    __shared__ float vs[16][64];
    int bh = blockIdx.x;
    int b = bh >> 3, h = bh & 7;
    int seg = blockIdx.y;
    int tid = threadIdx.x;
    int dd = tid >> 1;
    int ebase = (tid & 1) * 32;

    float acc[32];
#pragma unroll
    for (int j = 0; j < 32; j++) acc[j] = 0.f;

    int nstart = seg * (Nn / 4);
    for (int n0 = nstart; n0 < nstart + Nn / 4; n0 += 16) {
        {   // kf tile: 16x128 bf16 -> fp32 smem; 8 elts (16B) per thread
            int idx = tid * 8; int r = idx >> 7; int f = idx & 127;
            const __nv_bfloat162* src = (const __nv_bfloat162*)
                &d_kf[((size_t)bh * Nn + n0 + r) * Fn + f];
#pragma unroll
            for (int j = 0; j < 4; j++) {
                float2 v = __bfloat1622float2(src[j]);
                kfs[r][f + 2 * j]     = v.x;
                kfs[r][f + 2 * j + 1] = v.y;
            }
        }
        {   // v tile: 16x64 fp32
            int idx = tid * 4; int r = idx >> 6; int e = idx & 63;
            const float* src = &d_kv[((size_t)(b * Nn) + n0 + r) * 1024 + 512 + h * 64 + e];
            *(float4*)&vs[r][e] = *(const float4*)src;
        }
        __syncthreads();
#pragma unroll
        for (int nn = 0; nn < 16; nn++) {
            float a = kfs[nn][dd];
#pragma unroll
            for (int j = 0; j < 32; j++)
                acc[j] = fmaf(a, vs[nn][ebase + j], acc[j]);
        }
        __syncthreads();
    }
    const float inv_n = 1.f / (float)Nn;
    float* dst = &d_kvm[(size_t)bh * (Fn * 64) + dd * 64 + ebase];
#pragma unroll
    for (int j = 0; j < 32; j++) atomicAdd(&dst[j], acc[j] * inv_n);
}

// =====================================================================
// attention output (bf16 qf)
// =====================================================================
__global__ __launch_bounds__(256)
void attn_out_kernel()
{
    __shared__ float kvm_s[Fn * 64];
    __shared__ float qs[4][Fn];
    int bh = blockIdx.x;
    int b = bh >> 3, h = bh & 7;
    int tid = threadIdx.x;

    {
        const float* src = &d_kvm[(size_t)bh * (Fn * 64)];
#pragma unroll
        for (int i = 0; i < 8; i++) {
            int idx = (i * 256 + tid) * 4;
            *(float4*)&kvm_s[idx] = *(const float4*)&src[idx];
        }
    }
    __syncthreads();

    int e = tid & 63;
    int nsub = tid >> 6;
    int o1 = (e < 32) ? 0 : 64;
    int o2 = o1 ^ 64;
    int zi = (e < 32) ? 0 : 1;

    int nbase0 = blockIdx.y * 112;
    for (int it = 0; it < 28; it++) {
        int nbase = nbase0 + it * 4;
#pragma unroll
        for (int i = 0; i < 2; i++) {
            int idx = i * 256 + tid;
            int nn = idx >> 7, f = idx & 127;
            qs[nn][f] = __bfloat162float(
                d_qf[((size_t)bh * Nn + nbase + nn) * Fn + f]);
        }
        __syncthreads();

        int n = nbase + nsub;
        float acc = 0.f;
#pragma unroll
        for (int dlo = 0; dlo < 64; dlo++)
            acc = fmaf(qs[nsub][o1 + dlo], kvm_s[dlo * 64 + e], acc);
#pragma unroll
        for (int dlo = 0; dlo < 64; dlo++)
            acc = fmaf(qs[nsub][o2 + dlo], kvm_s[(64 + dlo) * 64 + e], acc);

        float zv = d_z[((size_t)bh * Nn + n) * 2 + zi];
        d_t[((size_t)(b * Nn) + n) * Cn + h * 64 + e] = acc * zv;
        __syncthreads();
    }
}

// =====================================================================
// depthwise 5x5 conv + gate, sliding register window (5 LDG/output).
// Stores d_t rounded to tf32 (A operand of gemm3).
// =====================================================================
__global__ __launch_bounds__(512)
void conv_gate_kernel(const float* __restrict__ dwc_w,
                      const float* __restrict__ dwc_b)
{
    __shared__ float ws[64 * 25];
    __shared__ float bs[64];
    int y = blockIdx.x;
    int b = blockIdx.y;
    int c = threadIdx.x;
    int d = c & 63;
    for (int i = c; i < 64 * 25; i += 512) ws[i] = dwc_w[i];
    if (c < 64) bs[c] = dwc_b[c];
    __syncthreads();

    const float* vbase = &d_kv[(size_t)(b * Nn) * 1024 + 512 + c];

    float win[5][5];
#pragma unroll
    for (int dy = 0; dy < 5; dy++) {
        int yy = y + dy - 2;
        bool yok = (unsigned)yy < HW;
#pragma unroll
        for (int j = 0; j < 5; j++) {
            int xx = j - 2;
            win[dy][j] = (yok && (unsigned)xx < HW)
                         ? vbase[(size_t)(yy * HW + xx) * 1024] : 0.f;
        }
    }

    for (int x = 0; x < HW; x++) {
        float acc = bs[d];
#pragma unroll
        for (int dy = 0; dy < 5; dy++)
#pragma unroll
            for (int j = 0; j < 5; j++)
                acc = fmaf(win[dy][j], ws[d * 25 + dy * 5 + j], acc);

        size_t i1 = (size_t)(b * Nn) + y * HW + x;
        float g = d_qg[i1 * 1024 + 512 + c];
        d_t[i1 * Cn + c] = to_tf32((d_t[i1 * Cn + c] + acc) * g);

        // shift window left, load column x+3
        int xx = x + 3;
        bool xok = xx < HW;
#pragma unroll
        for (int dy = 0; dy < 5; dy++) {
#pragma unroll
            for (int j = 0; j < 4; j++) win[dy][j] = win[dy][j + 1];
            int yy = y + dy - 2;
            win[dy][4] = (xok && (unsigned)yy < HW)
                         ? vbase[(size_t)(yy * HW + xx) * 1024] : 0.f;
        }
    }
}

// =====================================================================
// launch
// =====================================================================
extern "C" void kernel_launch(void* const* d_in, const int* in_sizes, int n_in,
                              void* d_out, int out_size)
{
    const float* x       = (const float*)d_in[0];
    const float* qg_w    = (const float*)d_in[1];
    const float* kv_w    = (const float*)d_in[2];
    const float* proj_w  = (const float*)d_in[3];
    const float* proj_b  = (const float*)d_in[4];
    const float* pos_enc = (const float*)d_in[5];
    const float* scale_p = (const float*)d_in[6];
    const float* power_p = (const float*)d_in[7];
    const float* dwc_w   = (const float*)d_in[8];
    const float* dwc_b   = (const float*)d_in[9];
    float* out = (float*)d_out;

    float *p_qg, *p_kv, *p_t, *p_wt1, *p_wt2, *p_wt3, *p_xr;
    cudaGetSymbolAddress((void**)&p_qg,  d_qg);
    cudaGetSymbolAddress((void**)&p_kv,  d_kv);
    cudaGetSymbolAddress((void**)&p_t,   d_t);
    cudaGetSymbolAddress((void**)&p_wt1, d_wt1);
    cudaGetSymbolAddress((void**)&p_wt2, d_wt2);
    cudaGetSymbolAddress((void**)&p_wt3, d_wt3);
    cudaGetSymbolAddress((void**)&p_xr,  d_xr);

    cudaFuncSetAttribute(gemm_mma, cudaFuncAttributeMaxDynamicSharedMemorySize,
                         GEMM_SMEM);

    dim3 tb(32, 8);
    // 0. weight transposes (tf32) + params + rounded x copy
    transpose_w<<<dim3(1024 / 32, 512 / 32), tb>>>(qg_w,   p_wt1, 1024);
    transpose_w<<<dim3(1024 / 32, 512 / 32), tb>>>(kv_w,   p_wt2, 1024);
    transpose_w<<<dim3(512 / 32,  512 / 32), tb>>>(proj_w, p_wt3, 512);
    prep_params<<<1, 512>>>(scale_p, power_p);
    round_x<<<Mrows * 512 / 1024, 256>>>(x);

    // 1. qg = x @ qg_w ; kv = x @ kv_w
    gemm_mma<<<dim3(1024 / GN, Mrows / GM), 256, GEMM_SMEM>>>(p_xr, p_wt1, nullptr, p_qg, 1024);
    gemm_mma<<<dim3(1024 / GN, Mrows / GM), 256, GEMM_SMEM>>>(p_xr, p_wt2, nullptr, p_kv, 1024);

    // 2. zero accumulators (before features' km atomics)
    zero_aux_kernel<<<1024, 256>>>();

    // 3. features + fused km
    features_kernel<<<Mrows / 16, 512>>>(pos_enc);

    // 4-6. linear-attention pieces
    z_kernel<<<(Bn * NH * Nn) / 8, 256>>>();
    kvm_kernel<<<dim3(Bn * NH, 4), 256>>>();
    attn_out_kernel<<<dim3(Bn * NH, Nn / 112), 256>>>();

    // 7. depthwise conv + gate (rounds d_t to tf32)
    conv_gate_kernel<<<dim3(HW, Bn), 512>>>(dwc_w, dwc_b);

    // 8. out = t @ proj_w + proj_b
    gemm_mma<<<dim3(512 / GN, Mrows / GM), 256, GEMM_SMEM>>>(p_t, p_wt3, proj_b, out, 512);
}

// round 6
// speedup vs baseline: 2.9654x; 1.6251x over previous
#include <cuda_runtime.h>
#include <cuda_bf16.h>
#include <math.h>
#include <stdint.h>

// ---------------- problem constants ----------------
#define Bn   16
#define Nn   3136        // 56*56
#define Cn   512
#define NH   8
#define HD   64
#define Fn   128         // 2*HD
#define Mrows (Bn*Nn)    // 50176
#define HW   56

// ---------------- scratch (device globals; no allocs allowed) --------------
__device__ __align__(16) float d_qgkv[Mrows * 2048];        // [b,n, q|g|k|v] (512 each)
__device__ __align__(16) float d_xr[Mrows * 512];           // tf32-rounded x
__device__ __align__(16) __nv_bfloat16 d_qf[Bn*NH*Nn*Fn];   // q_sim  [bh,n,128] bf16
__device__ __align__(16) __nv_bfloat16 d_kf[Bn*NH*Nn*Fn];   // kf     [bh,n,128] bf16
__device__ __align__(16) float d_km[Bn*NH*Fn];              // mean over n
__device__ __align__(16) float d_kvm[Bn*NH*Fn*64];          // [bh,d(128),e(64)]
__device__ __align__(16) float d_kvm2[Bn*NH*Fn*72];         // [bh,d(128),72] B for attn
__device__ __align__(16) float d_t [Mrows * Cn];            // (xo + vd) * g, tf32-rounded
__device__ __align__(16) float d_wtc[2048 * 512];           // [qg_w | kv_w]^T tf32
__device__ __align__(16) float d_wt3[512 * 512];            // proj_w^T
__device__ __align__(16) float d_scinv[Cn];                 // 1/softplus(scale_p)
__device__ __align__(16) float d_pw[Cn];                    // 1+4*sigmoid(power_p)

// =====================================================================
// helpers (baseline PTX only; no 'a'-gated features)
// =====================================================================
__device__ __forceinline__ uint32_t smem_u32(const void* p) {
    uint32_t a;
    asm("{ .reg .u64 t; cvta.to.shared.u64 t, %1; cvt.u32.u64 %0, t; }"
        : "=r"(a) : "l"(p));
    return a;
}

__device__ __forceinline__ float to_tf32(float x) {
    float r;
    asm("cvt.rna.tf32.f32 %0, %1;" : "=f"(r) : "f"(x));
    return r;
}

__device__ __forceinline__ void cp_async16(uint32_t saddr, const void* gaddr) {
    asm volatile("cp.async.ca.shared.global [%0], [%1], 16;"
                 :: "r"(saddr), "l"(gaddr) : "memory");
}
#define CP_COMMIT() asm volatile("cp.async.commit_group;" ::: "memory")
#define CP_WAIT(N)  asm volatile("cp.async.wait_group %0;" :: "n"(N) : "memory")

__device__ __forceinline__ void mma_tf32_16_8_8(float* c, const uint32_t* a,
                                                const uint32_t* b) {
    asm volatile(
        "mma.sync.aligned.m16n8k8.row.col.f32.tf32.tf32.f32 "
        "{%0,%1,%2,%3}, {%4,%5,%6,%7}, {%8,%9}, {%0,%1,%2,%3};"
        : "+f"(c[0]), "+f"(c[1]), "+f"(c[2]), "+f"(c[3])
        : "r"(a[0]), "r"(a[1]), "r"(a[2]), "r"(a[3]), "r"(b[0]), "r"(b[1]));
}

__device__ __forceinline__ uint32_t bf_as_tf32(uint16_t h) {
    __nv_bfloat16 b = *reinterpret_cast<__nv_bfloat16*>(&h);
    return __float_as_uint(__bfloat162float(b));
}

// =====================================================================
// tensor-core tf32 GEMM:  C[M,Nc] = A[M,512] @ Bt[Nc,512]^T  (+bias)
// A, Bt pre-rounded tf32. 128x128 CTA, BK=32, 256 thr, warp 64x32.
// =====================================================================
#define GM 128
#define GN 128
#define GK 32
#define SST 36
#define ABUF (128 * SST)
#define GEMM_SMEM (4 * ABUF * 4)        // 73728 bytes

__global__ __launch_bounds__(256, 2)
void gemm_mma(const float* __restrict__ A, const float* __restrict__ Bt,
              const float* __restrict__ bias, float* __restrict__ Cm, int Nc)
{
    extern __shared__ float sm[];
    float* smA[2] = { sm,            sm + ABUF };
    float* smB[2] = { sm + 2 * ABUF, sm + 3 * ABUF };
    const uint32_t suA[2] = { smem_u32(smA[0]), smem_u32(smA[1]) };
    const uint32_t suB[2] = { smem_u32(smB[0]), smem_u32(smB[1]) };

    const int tid = threadIdx.x;
    const int bn0 = blockIdx.x * GN;
    const int bm0 = blockIdx.y * GM;
    const int wid = tid >> 5, lane = tid & 31;
    const int wm = (wid & 1) * 64;
    const int wn = (wid >> 1) * 32;
    const int lr = lane >> 2, lc = lane & 3;

    float c[4][4][4];
#pragma unroll
    for (int mt = 0; mt < 4; mt++)
#pragma unroll
        for (int nt = 0; nt < 4; nt++)
#pragma unroll
            for (int j = 0; j < 4; j++) c[mt][nt][j] = 0.f;

    {
#pragma unroll
        for (int i = 0; i < 4; i++) {
            int idx = tid + i * 256;
            int r = idx >> 3, c4 = idx & 7;
            cp_async16(suA[0] + (r * SST + c4 * 4) * 4,
                       &A[(size_t)(bm0 + r) * 512 + c4 * 4]);
            cp_async16(suB[0] + (r * SST + c4 * 4) * 4,
                       &Bt[(size_t)(bn0 + r) * 512 + c4 * 4]);
        }
        CP_COMMIT();
    }

    const int NT = 512 / GK;
    int buf = 0;
    for (int t = 0; t < NT; t++) {
        if (t + 1 < NT) {
            int nb = buf ^ 1;
            int k0 = (t + 1) * GK;
#pragma unroll
            for (int i = 0; i < 4; i++) {
                int idx = tid + i * 256;
                int r = idx >> 3, c4 = idx & 7;
                cp_async16(suA[nb] + (r * SST + c4 * 4) * 4,
                           &A[(size_t)(bm0 + r) * 512 + k0 + c4 * 4]);
                cp_async16(suB[nb] + (r * SST + c4 * 4) * 4,
                           &Bt[(size_t)(bn0 + r) * 512 + k0 + c4 * 4]);
            }
            CP_COMMIT();
            CP_WAIT(1);
        } else {
            CP_WAIT(0);
        }
        __syncthreads();

        const float* As = smA[buf];
        const float* Bs = smB[buf];
#pragma unroll
        for (int kk = 0; kk < 4; kk++) {
            const int k0 = kk * 8;
            uint32_t a[4][4], b[4][2];
#pragma unroll
            for (int mt = 0; mt < 4; mt++) {
                int r = wm + mt * 16 + lr;
                a[mt][0] = __float_as_uint(As[r * SST + k0 + lc]);
                a[mt][1] = __float_as_uint(As[(r + 8) * SST + k0 + lc]);
                a[mt][2] = __float_as_uint(As[r * SST + k0 + lc + 4]);
                a[mt][3] = __float_as_uint(As[(r + 8) * SST + k0 + lc + 4]);
            }
#pragma unroll
            for (int nt = 0; nt < 4; nt++) {
                int n = wn + nt * 8 + lr;
                b[nt][0] = __float_as_uint(Bs[n * SST + k0 + lc]);
                b[nt][1] = __float_as_uint(Bs[n * SST + k0 + lc + 4]);
            }
#pragma unroll
            for (int mt = 0; mt < 4; mt++)
#pragma unroll
                for (int nt = 0; nt < 4; nt++)
                    mma_tf32_16_8_8(c[mt][nt], a[mt], b[nt]);
        }
        __syncthreads();
        buf ^= 1;
    }

#pragma unroll
    for (int mt = 0; mt < 4; mt++) {
        int row = bm0 + wm + mt * 16 + lr;
#pragma unroll
        for (int nt = 0; nt < 4; nt++) {
            int col = bn0 + wn + nt * 8 + lc * 2;
            float2 v0 = make_float2(c[mt][nt][0], c[mt][nt][1]);
            float2 v1 = make_float2(c[mt][nt][2], c[mt][nt][3]);
            if (bias) {
                float b0 = bias[col], b1 = bias[col + 1];
                v0.x += b0; v0.y += b1;
                v1.x += b0; v1.y += b1;
            }
            *(float2*)&Cm[(size_t)row * Nc + col] = v0;
            *(float2*)&Cm[(size_t)(row + 8) * Nc + col] = v1;
        }
    }
}

// =====================================================================
// combined weight transpose (qg_w | kv_w) -> d_wtc[2048][512], tf32
// =====================================================================
__global__ void transpose_qgkv(const float* __restrict__ qg_w,
                               const float* __restrict__ kv_w)
{
    __shared__ float t[32][33];
    int bx = blockIdx.x * 32;   // n in 0..2047
    int by = blockIdx.y * 32;   // k
    int x = threadIdx.x, y = threadIdx.y;
    const float* W = (bx < 1024) ? qg_w : kv_w;
    int nb = bx & 1023;
#pragma unroll
    for (int j = 0; j < 32; j += 8)
        t[y + j][x] = W[(size_t)(by + y + j) * 1024 + nb + x];
    __syncthreads();
#pragma unroll
    for (int j = 0; j < 32; j += 8)
        d_wtc[(size_t)(bx + y + j) * 512 + by + x] = to_tf32(t[x][y + j]);
}

__global__ void transpose_w(const float* __restrict__ W, float* __restrict__ Wt, int Nc)
{
    __shared__ float t[32][33];
    int bx = blockIdx.x * 32;
    int by = blockIdx.y * 32;
    int x = threadIdx.x, y = threadIdx.y;
#pragma unroll
    for (int j = 0; j < 32; j += 8)
        t[y + j][x] = W[(size_t)(by + y + j) * Nc + bx + x];
    __syncthreads();
#pragma unroll
    for (int j = 0; j < 32; j += 8)
        Wt[(size_t)(bx + y + j) * 512 + by + x] = to_tf32(t[x][y + j]);
}

// =====================================================================
// round x -> tf32 copy
// =====================================================================
__global__ void round_x(const float* __restrict__ x)
{
    size_t i = ((size_t)blockIdx.x * 256 + threadIdx.x) * 4;
    float4 v = *(const float4*)&x[i];
    v.x = to_tf32(v.x); v.y = to_tf32(v.y);
    v.z = to_tf32(v.z); v.w = to_tf32(v.w);
    *(float4*)&d_xr[i] = v;
}

// =====================================================================
// per-channel params
// =====================================================================
__global__ void prep_params(const float* __restrict__ scale_p,
                            const float* __restrict__ power_p)
{
    int c = threadIdx.x;
    d_scinv[c] = 1.f / log1pf(expf(scale_p[c]));
    d_pw[c] = 1.f + 4.f / (1.f + expf(-power_p[c]));
}

// =====================================================================
// features + fused km
// =====================================================================
__global__ __launch_bounds__(512)
void features_kernel(const float* __restrict__ pos_enc)
{
    int c   = threadIdx.x;
    int h   = c >> 6;
    int d   = c & 63;
    int bn0 = blockIdx.x * 16;
    int b   = bn0 / Nn;
    int n0  = bn0 - b * Nn;

    float scinv = d_scinv[c];
    float pw    = d_pw[c];
    float skp = 0.f, skn = 0.f;

#pragma unroll 4
    for (int i = 0; i < 16; i++) {
        int bn_ = bn0 + i;
        int n   = n0 + i;
        float qv  = d_qgkv[(size_t)bn_ * 2048 + c] * scinv;
        float kvv = (d_qgkv[(size_t)bn_ * 2048 + 1024 + c] + pos_enc[n * Cn + c]) * scinv;

        float qa = exp2f(pw * __log2f(fabsf(qv)));
        float ka = exp2f(pw * __log2f(fabsf(kvv)));
        float qp = (qv  > 0.f) ? qa : 0.f;
        float qn = (qv  < 0.f) ? qa : 0.f;
        float kp = (kvv > 0.f) ? ka : 0.f;
        float kn = (kvv < 0.f) ? ka : 0.f;

        size_t fbase = ((size_t)(b * NH + h) * Nn + n) * Fn;
        d_qf[fbase + d]      = __float2bfloat16_rn(qp);
        d_qf[fbase + 64 + d] = __float2bfloat16_rn(qn);
        d_kf[fbase + d]      = __float2bfloat16_rn(kp);
        d_kf[fbase + 64 + d] = __float2bfloat16_rn(kn);
        skp += kp; skn += kn;
    }
    const float inv_n = 1.f / (float)Nn;
    atomicAdd(&d_km[(b * NH + h) * Fn + d],      skp * inv_n);
    atomicAdd(&d_km[(b * NH + h) * Fn + 64 + d], skn * inv_n);
}

// =====================================================================
// zero km + kvm accumulators
// =====================================================================
__global__ void zero_aux_kernel()
{
    int i = blockIdx.x * blockDim.x + threadIdx.x;
    int stride = gridDim.x * blockDim.x;
    if (i < Bn * NH * Fn) d_km[i] = 0.f;
    for (int j = i; j < Bn * NH * Fn * 64; j += stride) d_kvm[j] = 0.f;
}

// =====================================================================
// kvm via mma: per (bh, seg): kvm[d,e] += sum_n kf[n,d] * v[n,e] / Nn
// CTA 256 thr, 8 warps (2 d x 4 e), warp tile 64x16, K=1568 per seg.
// =====================================================================
#define KV_SEG 1568

__global__ __launch_bounds__(256)
void kvm_mma()
{
    __shared__ __align__(16) uint16_t kfs[2][32][136];
    __shared__ __align__(16) float    vss[2][32][72];
    int bh = blockIdx.x, seg = blockIdx.y;
    int b = bh >> 3, h = bh & 7;
    int tid = threadIdx.x, wid = tid >> 5, lane = tid & 31;
    int lr = lane >> 2, lc = lane & 3;
    int wd = (wid & 1) * 64;
    int we = (wid >> 1) * 16;

    float c[4][2][4];
#pragma unroll
    for (int mt = 0; mt < 4; mt++)
#pragma unroll
        for (int nt = 0; nt < 2; nt++)
#pragma unroll
            for (int j = 0; j < 4; j++) c[mt][nt][j] = 0.f;

    int nbase = seg * KV_SEG;
#pragma unroll
    for (int j = 0; j < 2; j++) {          // prefetch tile 0
        int idx = tid + j * 256;
        int r = idx >> 4, cs = idx & 15;
        cp_async16(smem_u32(&kfs[0][r][cs * 8]),
                   &d_kf[((size_t)bh * Nn + nbase + r) * 128 + cs * 8]);
        cp_async16(smem_u32(&vss[0][r][cs * 4]),
                   &d_qgkv[((size_t)(b * Nn) + nbase + r) * 2048 + 1536 + h * 64 + cs * 4]);
    }
    CP_COMMIT();

    for (int t = 0; t < 49; t++) {
        if (t + 1 < 49) {
            int nb = (t + 1) & 1;
            int n0 = nbase + (t + 1) * 32;
#pragma unroll
            for (int j = 0; j < 2; j++) {
                int idx = tid + j * 256;
                int r = idx >> 4, cs = idx & 15;
                cp_async16(smem_u32(&kfs[nb][r][cs * 8]),
                           &d_kf[((size_t)bh * Nn + n0 + r) * 128 + cs * 8]);
                cp_async16(smem_u32(&vss[nb][r][cs * 4]),
                           &d_qgkv[((size_t)(b * Nn) + n0 + r) * 2048 + 1536 + h * 64 + cs * 4]);
            }
            CP_COMMIT();
            CP_WAIT(1);
        } else {
            CP_WAIT(0);
        }
        __syncthreads();
        int buf = t & 1;
#pragma unroll
        for (int kk = 0; kk < 4; kk++) {
            int k0 = kk * 8;
            uint32_t a[4][4], bf[2][2];
#pragma unroll
            for (int mt = 0; mt < 4; mt++) {
                int db = wd + mt * 16;
                a[mt][0] = bf_as_tf32(kfs[buf][k0 + lc][db + lr]);
                a[mt][1] = bf_as_tf32(kfs[buf][k0 + lc][db + lr + 8]);
                a[mt][2] = bf_as_tf32(kfs[buf][k0 + lc + 4][db + lr]);
                a[mt][3] = bf_as_tf32(kfs[buf][k0 + lc + 4][db + lr + 8]);
            }
#pragma unroll
            for (int nt = 0; nt < 2; nt++) {
                int eb = we + nt * 8;
                bf[nt][0] = __float_as_uint(vss[buf][k0 + lc][eb + lr]);
                bf[nt][1] = __float_as_uint(vss[buf][k0 + lc + 4][eb + lr]);
            }
#pragma unroll
            for (int mt = 0; mt < 4; mt++)
#pragma unroll
                for (int nt = 0; nt < 2; nt++)
                    mma_tf32_16_8_8(c[mt][nt], a[mt], bf[nt]);
        }
        __syncthreads();
    }

    const float inv_n = 1.f / (float)Nn;
    float* dst = &d_kvm[(size_t)bh * 8192];
#pragma unroll
    for (int mt = 0; mt < 4; mt++) {
        int d0 = wd + mt * 16 + lr;
#pragma unroll
        for (int nt = 0; nt < 2; nt++) {
            int e0 = we + nt * 8 + 2 * lc;
            atomicAdd(&dst[d0 * 64 + e0],           c[mt][nt][0] * inv_n);
            atomicAdd(&dst[d0 * 64 + e0 + 1],       c[mt][nt][1] * inv_n);
            atomicAdd(&dst[(d0 + 8) * 64 + e0],     c[mt][nt][2] * inv_n);
            atomicAdd(&dst[(d0 + 8) * 64 + e0 + 1], c[mt][nt][3] * inv_n);
        }
    }
}

// =====================================================================
// build KVM2[bh][128][72]: cols<32: kvm[d][c]; 32..63: kvm[d^64][c];
// 64: km[d]; 65: km[d^64]; 66..71: 0
// =====================================================================
__global__ void build_kvm2()
{
    int bh = blockIdx.x;
    const float* kvm = &d_kvm[(size_t)bh * 8192];
    const float* km  = &d_km[bh * 128];
    float* out = &d_kvm2[(size_t)bh * 9216];
    for (int i = threadIdx.x; i < 128 * 72; i += 256) {
        int dd = i / 72, col = i - dd * 72;
        float v;
        if (col < 32)       v = kvm[dd * 64 + col];
        else if (col < 64)  v = kvm[(dd ^ 64) * 64 + col];
        else if (col == 64) v = km[dd];
        else if (col == 65) v = km[dd ^ 64];
        else                v = 0.f;
        out[i] = v;
    }
}

// =====================================================================
// attention via mma: per (m-tile 64, bh): C[64,72] = qf_tile @ KVM2.
// cols 64/65 are the z denominators; epilogue applies z, stages smem,
// writes coalesced into d_t.
// =====================================================================
#define ATT_SMEM (36864 + 17408)     // B f32 [128][72] + A bf16 [64][136]

__global__ __launch_bounds__(128)
void attn_mma()
{
    extern __shared__ char smx[];
    float*    Bsm = (float*)smx;                   // [128][72]
    uint16_t* Asm = (uint16_t*)(smx + 36864);      // [64][136]
    int m0 = blockIdx.x * 64, bh = blockIdx.y;
    int b = bh >> 3, h = bh & 7;
    int tid = threadIdx.x, wid = tid >> 5, lane = tid & 31;
    int lr = lane >> 2, lc = lane & 3;
    int wm = wid * 16;

    {
        const char* bsrc = (const char*)&d_kvm2[(size_t)bh * 9216];
#pragma unroll
        for (int j = 0; j < 18; j++) {
            int idx = tid + j * 128;
            cp_async16(smem_u32((char*)Bsm + idx * 16), bsrc + idx * 16);
        }
#pragma unroll
        for (int j = 0; j < 8; j++) {
            int idx = tid + j * 128;
            int r = idx >> 4, cs = idx & 15;
            cp_async16(smem_u32(&Asm[r * 136 + cs * 8]),
                       &d_qf[((size_t)bh * Nn + m0 + r) * 128 + cs * 8]);
        }
        CP_COMMIT(); CP_WAIT(0);
    }
    __syncthreads();

    float c[9][4];
#pragma unroll
    for (int nt = 0; nt < 9; nt++)
#pragma unroll
        for (int j = 0; j < 4; j++) c[nt][j] = 0.f;

#pragma unroll
    for (int kt = 0; kt < 16; kt++) {
        int k0 = kt * 8;
        uint32_t a[4];
        a[0] = bf_as_tf32(Asm[(wm + lr) * 136 + k0 + lc]);
        a[1] = bf_as_tf32(Asm[(wm + lr + 8) * 136 + k0 + lc]);
        a[2] = bf_as_tf32(Asm[(wm + lr) * 136 + k0 + lc + 4]);
        a[3] = bf_as_tf32(Asm[(wm + lr + 8) * 136 + k0 + lc + 4]);
#pragma unroll
        for (int nt = 0; nt < 9; nt++) {
            uint32_t bb[2];
            bb[0] = __float_as_uint(Bsm[(k0 + lc) * 72 + nt * 8 + lr]);
            bb[1] = __float_as_uint(Bsm[(k0 + lc + 4) * 72 + nt * 8 + lr]);
            mma_tf32_16_8_8(c[nt], a, bb);
        }
    }

    // z from cols 64/65 (held by lc==0 lanes of n-tile 8)
    int src = lane & 28;
    float den1a = __shfl_sync(0xffffffffu, c[8][0], src);
    float den2a = __shfl_sync(0xffffffffu, c[8][1], src);
    float den1b = __shfl_sync(0xffffffffu, c[8][2], src);
    float den2b = __shfl_sync(0xffffffffu, c[8][3], src);
    float z1a = 1.f / (den1a + 1e-6f), z2a = 1.f / (den2a + 1e-6f);
    float z1b = 1.f / (den1b + 1e-6f), z2b = 1.f / (den2b + 1e-6f);

    __syncthreads();                 // done reading Bsm
    float* Osm = Bsm;                // [64][72]
#pragma unroll
    for (int nt = 0; nt < 8; nt++) {
        int col = nt * 8 + 2 * lc;
        float za = (col < 32) ? z1a : z2a;
        float zb = (col < 32) ? z1b : z2b;
        Osm[(wm + lr) * 72 + col]         = c[nt][0] * za;
        Osm[(wm + lr) * 72 + col + 1]     = c[nt][1] * za;
        Osm[(wm + lr + 8) * 72 + col]     = c[nt][2] * zb;
        Osm[(wm + lr + 8) * 72 + col + 1] = c[nt][3] * zb;
    }
    __syncthreads();
#pragma unroll
    for (int j = 0; j < 8; j++) {
        int idx = tid + j * 128;
        int r = idx >> 4, c4 = (idx & 15) * 4;
        float4 v = *(float4*)&Osm[r * 72 + c4];
        *(float4*)&d_t[((size_t)(b * Nn) + m0 + r) * 512 + h * 64 + c4] = v;
    }
}

// =====================================================================
// depthwise 5x5 conv + gate, sliding window; stores d_t tf32-rounded
// =====================================================================
__global__ __launch_bounds__(512)
void conv_gate_kernel(const float* __restrict__ dwc_w,
                      const float* __restrict__ dwc_b)
{
    __shared__ float ws[64 * 25];
    __shared__ float bs[64];
    int y = blockIdx.x;
    int b = blockIdx.y;
    int c = threadIdx.x;
    int d = c & 63;
    for (int i = c; i < 64 * 25; i += 512) ws[i] = dwc_w[i];
    if (c < 64) bs[c] = dwc_b[c];
    __syncthreads();

    const float* vbase = &d_qgkv[(size_t)(b * Nn) * 2048 + 1536 + c];

    float win[5][5];
#pragma unroll
    for (int dy = 0; dy < 5; dy++) {
        int yy = y + dy - 2;
        bool yok = (unsigned)yy < HW;
#pragma unroll
        for (int j = 0; j < 5; j++) {
            int xx = j - 2;
            win[dy][j] = (yok && (unsigned)xx < HW)
                         ? vbase[(size_t)(yy * HW + xx) * 2048] : 0.f;
        }
    }

    for (int x = 0; x < HW; x++) {
        float acc = bs[d];
#pragma unroll
        for (int dy = 0; dy < 5; dy++)
#pragma unroll
            for (int j = 0; j < 5; j++)
                acc = fmaf(win[dy][j], ws[d * 25 + dy * 5 + j], acc);

        size_t i1 = (size_t)(b * Nn) + y * HW + x;
        float g = d_qgkv[i1 * 2048 + 512 + c];
        d_t[i1 * Cn + c] = to_tf32((d_t[i1 * Cn + c] + acc) * g);

        int xx = x + 3;
        bool xok = xx < HW;
#pragma unroll
        for (int dy = 0; dy < 5; dy++) {
#pragma unroll
            for (int j = 0; j < 4; j++) win[dy][j] = win[dy][j + 1];
            int yy = y + dy - 2;
            win[dy][4] = (xok && (unsigned)yy < HW)
                         ? vbase[(size_t)(yy * HW + xx) * 2048] : 0.f;
        }
    }
}

// =====================================================================
// launch  (order chosen so launch #3 == big gemm for ncu capture)
// =====================================================================
extern "C" void kernel_launch(void* const* d_in, const int* in_sizes, int n_in,
                              void* d_out, int out_size)
{
    const float* x       = (const float*)d_in[0];
    const float* qg_w    = (const float*)d_in[1];
    const float* kv_w    = (const float*)d_in[2];
    const float* proj_w  = (const float*)d_in[3];
    const float* proj_b  = (const float*)d_in[4];
    const float* pos_enc = (const float*)d_in[5];
    const float* scale_p = (const float*)d_in[6];
    const float* power_p = (const float*)d_in[7];
    const float* dwc_w   = (const float*)d_in[8];
    const float* dwc_b   = (const float*)d_in[9];
    float* out = (float*)d_out;

    float *p_qgkv, *p_t, *p_wtc, *p_wt3, *p_xr;
    cudaGetSymbolAddress((void**)&p_qgkv, d_qgkv);
    cudaGetSymbolAddress((void**)&p_t,    d_t);
    cudaGetSymbolAddress((void**)&p_wtc,  d_wtc);
    cudaGetSymbolAddress((void**)&p_wt3,  d_wt3);
    cudaGetSymbolAddress((void**)&p_xr,   d_xr);

    cudaFuncSetAttribute(gemm_mma, cudaFuncAttributeMaxDynamicSharedMemorySize,
                         GEMM_SMEM);
    cudaFuncSetAttribute(attn_mma, cudaFuncAttributeMaxDynamicSharedMemorySize,
                         ATT_SMEM);

    dim3 tb(32, 8);
    prep_params<<<1, 512>>>(scale_p, power_p);                       // 0
    round_x<<<Mrows * 512 / 1024, 256>>>(x);                         // 1
    transpose_qgkv<<<dim3(64, 16), tb>>>(qg_w, kv_w);                // 2
    gemm_mma<<<dim3(16, Mrows / GM), 256, GEMM_SMEM>>>(              // 3 (profiled)
        p_xr, p_wtc, nullptr, p_qgkv, 2048);
    transpose_w<<<dim3(16, 16), tb>>>(proj_w, p_wt3, 512);           // 4
    zero_aux_kernel<<<1024, 256>>>();                                // 5
    features_kernel<<<Mrows / 16, 512>>>(pos_enc);                   // 6
    kvm_mma<<<dim3(Bn * NH, 2), 256>>>();                            // 7
    build_kvm2<<<Bn * NH, 256>>>();                                  // 8
    attn_mma<<<dim3(Nn / 64, Bn * NH), 128, ATT_SMEM>>>();           // 9
    conv_gate_kernel<<<dim3(HW, Bn), 512>>>(dwc_w, dwc_b);           // 10
    gemm_mma<<<dim3(4, Mrows / GM), 256, GEMM_SMEM>>>(               // 11
        p_t, p_wt3, proj_b, out, 512);
}

// round 7
// speedup vs baseline: 3.1453x; 1.0607x over previous
#include <cuda_runtime.h>
#include <cuda_bf16.h>
#include <math.h>
#include <stdint.h>

// ---------------- problem constants ----------------
#define Bn   16
#define Nn   3136        // 56*56
#define Cn   512
#define NH   8
#define HD   64
#define Fn   128         // 2*HD
#define Mrows (Bn*Nn)    // 50176
#define HW   56

// ---------------- scratch (device globals; no allocs allowed) --------------
__device__ __align__(16) float d_qgkv[Mrows * 2048];        // [b,n, q|g|k|v] (512 each)
__device__ __align__(16) float d_xr[Mrows * 512];           // x, tf32, FRAGMENT layout
__device__ __align__(16) __nv_bfloat16 d_qf[Bn*NH*Nn*Fn];   // q_sim  [bh,n,128] bf16
__device__ __align__(16) __nv_bfloat16 d_kf[Bn*NH*Nn*Fn];   // kf     [bh,n,128] bf16
__device__ __align__(16) float d_km[Bn*NH*Fn];              // mean over n
__device__ __align__(16) float d_kvm[Bn*NH*Fn*64];          // [bh,d(128),e(64)]
__device__ __align__(16) float d_kvm2[Bn*NH*Fn*72];         // [bh,d(128),72] B for attn
__device__ __align__(16) float d_t [Mrows * Cn];            // (xo+vd)*g, tf32, FRAGMENT layout
__device__ __align__(16) float d_wtc[2048 * 512];           // [qg_w|kv_w]^T tf32, FRAGMENT
__device__ __align__(16) float d_wt3[512 * 512];            // proj_w^T tf32, FRAGMENT
__device__ __align__(16) float d_scinv[Cn];
__device__ __align__(16) float d_pw[Cn];

// =====================================================================
// helpers (baseline PTX only)
// =====================================================================
__device__ __forceinline__ uint32_t smem_u32(const void* p) {
    uint32_t a;
    asm("{ .reg .u64 t; cvta.to.shared.u64 t, %1; cvt.u32.u64 %0, t; }"
        : "=r"(a) : "l"(p));
    return a;
}

__device__ __forceinline__ float to_tf32(float x) {
    float r;
    asm("cvt.rna.tf32.f32 %0, %1;" : "=f"(r) : "f"(x));
    return r;
}

__device__ __forceinline__ void cp_async16(uint32_t saddr, const void* gaddr) {
    asm volatile("cp.async.ca.shared.global [%0], [%1], 16;"
                 :: "r"(saddr), "l"(gaddr) : "memory");
}
#define CP_COMMIT() asm volatile("cp.async.commit_group;" ::: "memory")
#define CP_WAIT(N)  asm volatile("cp.async.wait_group %0;" :: "n"(N) : "memory")

__device__ __forceinline__ void mma_tf32_16_8_8(float* c, const uint32_t* a,
                                                uint32_t b0, uint32_t b1) {
    asm volatile(
        "mma.sync.aligned.m16n8k8.row.col.f32.tf32.tf32.f32 "
        "{%0,%1,%2,%3}, {%4,%5,%6,%7}, {%8,%9}, {%0,%1,%2,%3};"
        : "+f"(c[0]), "+f"(c[1]), "+f"(c[2]), "+f"(c[3])
        : "r"(a[0]), "r"(a[1]), "r"(a[2]), "r"(a[3]), "r"(b0), "r"(b1));
}

__device__ __forceinline__ uint32_t bf_as_tf32(uint16_t h) {
    __nv_bfloat16 b = *reinterpret_cast<__nv_bfloat16*>(&h);
    return __float_as_uint(__bfloat162float(b));
}

// fragment-order permutation for K=512 operand panels of 128 rows.
// word w at lane L of 512B block (kblock, g): w = (r>>3&1) + 2*(k>>2&1),
// lane = (r&7)*4 + (k&3), block = (k>>3)*8 + (r>>4&7), panel = r>>7.
__device__ __forceinline__ size_t perm_idx(int r, int k) {
    return (size_t)(r >> 7) * 65536
         + (size_t)((((k >> 3) * 8 + ((r >> 4) & 7)) << 7)
         + (((r & 7) * 4 + (k & 3)) << 2)
         + ((r >> 3) & 1) + (((k >> 2) & 1) << 1));
}

// =====================================================================
// tensor-core tf32 GEMM: C[M,Nc] = A[M,512] @ Bt[Nc,512]^T (+bias)
// A, Bt in FRAGMENT layout. CTA 128x256, 8 warps (2m x 4n), warp 64x64.
// All fragment loads are conflict-free LDS.128.
// =====================================================================
#define GEMM_SMEM (2 * 12288 * 4)      // 2 stages x (4K A + 8K B floats) = 98304 B

__global__ __launch_bounds__(256, 1)
void gemm_mma(const float* __restrict__ A, const float* __restrict__ Bt,
              const float* __restrict__ bias, float* __restrict__ Cm, int Nc)
{
    extern __shared__ float sm[];
    float* stage[2] = { sm, sm + 12288 };
    const int tid = threadIdx.x;
    const int bn0 = blockIdx.x * 256;
    const int bm_panel = blockIdx.y;
    const int wid = tid >> 5, lane = tid & 31;
    const int lr = lane >> 2, lc = lane & 3;
    const int wm  = (wid & 1) * 64;          // warp M offset
    const int wm4 = (wid & 1) * 4;           // A 16-row-group base
    const int wn  = (wid >> 1) * 64;         // warp N offset
    const int wng = (wid >> 1) * 4;          // B 16-row-group base

    const float* Ab  = A  + (size_t)bm_panel * 65536;
    const float* Bb0 = Bt + (size_t)(bn0 >> 7) * 65536;
    const float* Bb1 = Bb0 + 65536;

    float c[4][8][4];
#pragma unroll
    for (int mt = 0; mt < 4; mt++)
#pragma unroll
        for (int nt = 0; nt < 8; nt++)
#pragma unroll
            for (int j = 0; j < 4; j++) c[mt][nt][j] = 0.f;

    // stage issue: A 1024 16B-chunks, B 2x1024
    auto issue_stage = [&](int buf, int t) {
        uint32_t sa = smem_u32(stage[buf]);
        const float* as = Ab  + t * 4096;
        const float* b0 = Bb0 + t * 4096;
        const float* b1 = Bb1 + t * 4096;
#pragma unroll
        for (int i = 0; i < 4; i++) {
            int ch = tid + i * 256;
            cp_async16(sa + ch * 16, as + ch * 4);
        }
#pragma unroll
        for (int i = 0; i < 4; i++) {
            int ch = tid + i * 256;
            cp_async16(sa + 16384 + ch * 16, b0 + ch * 4);
        }
#pragma unroll
        for (int i = 0; i < 4; i++) {
            int ch = tid + i * 256;
            cp_async16(sa + 32768 + ch * 16, b1 + ch * 4);
        }
        CP_COMMIT();
    };

    issue_stage(0, 0);

    int buf = 0;
    for (int t = 0; t < 16; t++) {
        if (t + 1 < 16) {
            issue_stage(buf ^ 1, t + 1);
            CP_WAIT(1);
        } else {
            CP_WAIT(0);
        }
        __syncthreads();

        const float4* sa4 = (const float4*)stage[buf];
        const float4* sb4 = (const float4*)(stage[buf] + 4096);
#pragma unroll
        for (int kk = 0; kk < 4; kk++) {
            uint32_t a[4][4];
            float4 bv[4];
#pragma unroll
            for (int mt = 0; mt < 4; mt++) {
                float4 v = sa4[(kk * 8 + wm4 + mt) * 32 + lane];
                a[mt][0] = __float_as_uint(v.x);
                a[mt][1] = __float_as_uint(v.y);
                a[mt][2] = __float_as_uint(v.z);
                a[mt][3] = __float_as_uint(v.w);
            }
#pragma unroll
            for (int p = 0; p < 4; p++) {
                int g = wng + p;
                bv[p] = sb4[(g >> 3) * 1024 + (kk * 8 + (g & 7)) * 32 + lane];
            }
#pragma unroll
            for (int mt = 0; mt < 4; mt++)
#pragma unroll
                for (int p = 0; p < 4; p++) {
                    mma_tf32_16_8_8(c[mt][2 * p],
                                    a[mt], __float_as_uint(bv[p].x),
                                           __float_as_uint(bv[p].z));
                    mma_tf32_16_8_8(c[mt][2 * p + 1],
                                    a[mt], __float_as_uint(bv[p].y),
                                           __float_as_uint(bv[p].w));
                }
        }
        __syncthreads();
        buf ^= 1;
    }

#pragma unroll
    for (int mt = 0; mt < 4; mt++) {
        int row = bm_panel * 128 + wm + mt * 16 + lr;
#pragma unroll
        for (int nt = 0; nt < 8; nt++) {
            int col = bn0 + wn + nt * 8 + lc * 2;
            float2 v0 = make_float2(c[mt][nt][0], c[mt][nt][1]);
            float2 v1 = make_float2(c[mt][nt][2], c[mt][nt][3]);
            if (bias) {
                float b0 = bias[col], b1 = bias[col + 1];
                v0.x += b0; v0.y += b1;
                v1.x += b0; v1.y += b1;
            }
            *(float2*)&Cm[(size_t)row * Nc + col] = v0;
            *(float2*)&Cm[(size_t)(row + 8) * Nc + col] = v1;
        }
    }
}

// =====================================================================
// weight transposes -> fragment layout, tf32
// =====================================================================
__global__ void transpose_qgkv(const float* __restrict__ qg_w,
                               const float* __restrict__ kv_w)
{
    __shared__ float t[32][33];
    int bx = blockIdx.x * 32;   // n in 0..2047
    int by = blockIdx.y * 32;   // k
    int x = threadIdx.x, y = threadIdx.y;
    const float* W = (bx < 1024) ? qg_w : kv_w;
    int nb = bx & 1023;
#pragma unroll
    for (int j = 0; j < 32; j += 8)
        t[y + j][x] = W[(size_t)(by + y + j) * 1024 + nb + x];
    __syncthreads();
#pragma unroll
    for (int j = 0; j < 32; j += 8)
        d_wtc[perm_idx(bx + y + j, by + x)] = to_tf32(t[x][y + j]);
}

__global__ void transpose_w(const float* __restrict__ W, float* __restrict__ Wt, int Nc)
{
    __shared__ float t[32][33];
    int bx = blockIdx.x * 32;
    int by = blockIdx.y * 32;
    int x = threadIdx.x, y = threadIdx.y;
#pragma unroll
    for (int j = 0; j < 32; j += 8)
        t[y + j][x] = W[(size_t)(by + y + j) * Nc + bx + x];
    __syncthreads();
#pragma unroll
    for (int j = 0; j < 32; j += 8)
        Wt[perm_idx(bx + y + j, by + x)] = to_tf32(t[x][y + j]);
}

// =====================================================================
// x -> tf32 fragment layout
// =====================================================================
__global__ void permute_x(const float* __restrict__ x)
{
    int idx = blockIdx.x * 256 + threadIdx.x;   // float4 index
    int r = idx >> 7;
    int k = (idx & 127) * 4;
    float4 v = ((const float4*)x)[idx];
    size_t base = perm_idx(r, k);
    d_xr[base]      = to_tf32(v.x);
    d_xr[base + 4]  = to_tf32(v.y);
    d_xr[base + 8]  = to_tf32(v.z);
    d_xr[base + 12] = to_tf32(v.w);
}

// =====================================================================
// per-channel params
// =====================================================================
__global__ void prep_params(const float* __restrict__ scale_p,
                            const float* __restrict__ power_p)
{
    int c = threadIdx.x;
    d_scinv[c] = 1.f / log1pf(expf(scale_p[c]));
    d_pw[c] = 1.f + 4.f / (1.f + expf(-power_p[c]));
}

// =====================================================================
// features + fused km
// =====================================================================
__global__ __launch_bounds__(512)
void features_kernel(const float* __restrict__ pos_enc)
{
    int c   = threadIdx.x;
    int h   = c >> 6;
    int d   = c & 63;
    int bn0 = blockIdx.x * 16;
    int b   = bn0 / Nn;
    int n0  = bn0 - b * Nn;

    float scinv = d_scinv[c];
    float pw    = d_pw[c];
    float skp = 0.f, skn = 0.f;

#pragma unroll 4
    for (int i = 0; i < 16; i++) {
        int bn_ = bn0 + i;
        int n   = n0 + i;
        float qv  = d_qgkv[(size_t)bn_ * 2048 + c] * scinv;
        float kvv = (d_qgkv[(size_t)bn_ * 2048 + 1024 + c] + pos_enc[n * Cn + c]) * scinv;

        float qa = exp2f(pw * __log2f(fabsf(qv)));
        float ka = exp2f(pw * __log2f(fabsf(kvv)));
        float qp = (qv  > 0.f) ? qa : 0.f;
        float qn = (qv  < 0.f) ? qa : 0.f;
        float kp = (kvv > 0.f) ? ka : 0.f;
        float kn = (kvv < 0.f) ? ka : 0.f;

        size_t fbase = ((size_t)(b * NH + h) * Nn + n) * Fn;
        d_qf[fbase + d]      = __float2bfloat16_rn(qp);
        d_qf[fbase + 64 + d] = __float2bfloat16_rn(qn);
        d_kf[fbase + d]      = __float2bfloat16_rn(kp);
        d_kf[fbase + 64 + d] = __float2bfloat16_rn(kn);
        skp += kp; skn += kn;
    }
    const float inv_n = 1.f / (float)Nn;
    atomicAdd(&d_km[(b * NH + h) * Fn + d],      skp * inv_n);
    atomicAdd(&d_km[(b * NH + h) * Fn + 64 + d], skn * inv_n);
}

// =====================================================================
// zero km + kvm accumulators
// =====================================================================
__global__ void zero_aux_kernel()
{
    int i = blockIdx.x * blockDim.x + threadIdx.x;
    int stride = gridDim.x * blockDim.x;
    if (i < Bn * NH * Fn) d_km[i] = 0.f;
    for (int j = i; j < Bn * NH * Fn * 64; j += stride) d_kvm[j] = 0.f;
}

// =====================================================================
// kvm via mma (unchanged from R6)
// =====================================================================
#define KV_SEG 1568

__global__ __launch_bounds__(256)
void kvm_mma()
{
    __shared__ __align__(16) uint16_t kfs[2][32][136];
    __shared__ __align__(16) float    vss[2][32][72];
    int bh = blockIdx.x, seg = blockIdx.y;
    int b = bh >> 3, h = bh & 7;
    int tid = threadIdx.x, wid = tid >> 5, lane = tid & 31;
    int lr = lane >> 2, lc = lane & 3;
    int wd = (wid & 1) * 64;
    int we = (wid >> 1) * 16;

    float c[4][2][4];
#pragma unroll
    for (int mt = 0; mt < 4; mt++)
#pragma unroll
        for (int nt = 0; nt < 2; nt++)
#pragma unroll
            for (int j = 0; j < 4; j++) c[mt][nt][j] = 0.f;

    int nbase = seg * KV_SEG;
#pragma unroll
    for (int j = 0; j < 2; j++) {
        int idx = tid + j * 256;
        int r = idx >> 4, cs = idx & 15;
        cp_async16(smem_u32(&kfs[0][r][cs * 8]),
                   &d_kf[((size_t)bh * Nn + nbase + r) * 128 + cs * 8]);
        cp_async16(smem_u32(&vss[0][r][cs * 4]),
                   &d_qgkv[((size_t)(b * Nn) + nbase + r) * 2048 + 1536 + h * 64 + cs * 4]);
    }
    CP_COMMIT();

    for (int t = 0; t < 49; t++) {
        if (t + 1 < 49) {
            int nb = (t + 1) & 1;
            int n0 = nbase + (t + 1) * 32;
#pragma unroll
            for (int j = 0; j < 2; j++) {
                int idx = tid + j * 256;
                int r = idx >> 4, cs = idx & 15;
                cp_async16(smem_u32(&kfs[nb][r][cs * 8]),
                           &d_kf[((size_t)bh * Nn + n0 + r) * 128 + cs * 8]);
                cp_async16(smem_u32(&vss[nb][r][cs * 4]),
                           &d_qgkv[((size_t)(b * Nn) + n0 + r) * 2048 + 1536 + h * 64 + cs * 4]);
            }
            CP_COMMIT();
            CP_WAIT(1);
        } else {
            CP_WAIT(0);
        }
        __syncthreads();
        int buf = t & 1;
#pragma unroll
        for (int kk = 0; kk < 4; kk++) {
            int k0 = kk * 8;
            uint32_t a[4][4];
#pragma unroll
            for (int mt = 0; mt < 4; mt++) {
                int db = wd + mt * 16;
                a[mt][0] = bf_as_tf32(kfs[buf][k0 + lc][db + lr]);
                a[mt][1] = bf_as_tf32(kfs[buf][k0 + lc][db + lr + 8]);
                a[mt][2] = bf_as_tf32(kfs[buf][k0 + lc + 4][db + lr]);
                a[mt][3] = bf_as_tf32(kfs[buf][k0 + lc + 4][db + lr + 8]);
            }
#pragma unroll
            for (int nt = 0; nt < 2; nt++) {
                int eb = we + nt * 8;
                uint32_t b0 = __float_as_uint(vss[buf][k0 + lc][eb + lr]);
                uint32_t b1 = __float_as_uint(vss[buf][k0 + lc + 4][eb + lr]);
#pragma unroll
                for (int mt = 0; mt < 4; mt++)
                    mma_tf32_16_8_8(c[mt][nt], a[mt], b0, b1);
            }
        }
        __syncthreads();
    }

    const float inv_n = 1.f / (float)Nn;
    float* dst = &d_kvm[(size_t)bh * 8192];
#pragma unroll
    for (int mt = 0; mt < 4; mt++) {
        int d0 = wd + mt * 16 + lr;
#pragma unroll
        for (int nt = 0; nt < 2; nt++) {
            int e0 = we + nt * 8 + 2 * lc;
            atomicAdd(&dst[d0 * 64 + e0],           c[mt][nt][0] * inv_n);
            atomicAdd(&dst[d0 * 64 + e0 + 1],       c[mt][nt][1] * inv_n);
            atomicAdd(&dst[(d0 + 8) * 64 + e0],     c[mt][nt][2] * inv_n);
            atomicAdd(&dst[(d0 + 8) * 64 + e0 + 1], c[mt][nt][3] * inv_n);
        }
    }
}

// =====================================================================
// build KVM2
// =====================================================================
__global__ void build_kvm2()
{
    int bh = blockIdx.x;
    const float* kvm = &d_kvm[(size_t)bh * 8192];
    const float* km  = &d_km[bh * 128];
    float* out = &d_kvm2[(size_t)bh * 9216];
    for (int i = threadIdx.x; i < 128 * 72; i += 256) {
        int dd = i / 72, col = i - dd * 72;
        float v;
        if (col < 32)       v = kvm[dd * 64 + col];
        else if (col < 64)  v = kvm[(dd ^ 64) * 64 + col];
        else if (col == 64) v = km[dd];
        else if (col == 65) v = km[dd ^ 64];
        else                v = 0.f;
        out[i] = v;
    }
}

// =====================================================================
// attention via mma; scatter-stores d_t in FRAGMENT layout
// =====================================================================
#define ATT_SMEM (36864 + 17408)

__global__ __launch_bounds__(128)
void attn_mma()
{
    extern __shared__ char smx[];
    float*    Bsm = (float*)smx;                   // [128][72]
    uint16_t* Asm = (uint16_t*)(smx + 36864);      // [64][136]
    int m0 = blockIdx.x * 64, bh = blockIdx.y;
    int b = bh >> 3, h = bh & 7;
    int tid = threadIdx.x, wid = tid >> 5, lane = tid & 31;
    int lr = lane >> 2, lc = lane & 3;
    int wm = wid * 16;

    {
        const char* bsrc = (const char*)&d_kvm2[(size_t)bh * 9216];
#pragma unroll
        for (int j = 0; j < 18; j++) {
            int idx = tid + j * 128;
            cp_async16(smem_u32((char*)Bsm + idx * 16), bsrc + idx * 16);
        }
#pragma unroll
        for (int j = 0; j < 8; j++) {
            int idx = tid + j * 128;
            int r = idx >> 4, cs = idx & 15;
            cp_async16(smem_u32(&Asm[r * 136 + cs * 8]),
                       &d_qf[((size_t)bh * Nn + m0 + r) * 128 + cs * 8]);
        }
        CP_COMMIT(); CP_WAIT(0);
    }
    __syncthreads();

    float c[9][4];
#pragma unroll
    for (int nt = 0; nt < 9; nt++)
#pragma unroll
        for (int j = 0; j < 4; j++) c[nt][j] = 0.f;

#pragma unroll
    for (int kt = 0; kt < 16; kt++) {
        int k0 = kt * 8;
        uint32_t a[4];
        a[0] = bf_as_tf32(Asm[(wm + lr) * 136 + k0 + lc]);
        a[1] = bf_as_tf32(Asm[(wm + lr + 8) * 136 + k0 + lc]);
        a[2] = bf_as_tf32(Asm[(wm + lr) * 136 + k0 + lc + 4]);
        a[3] = bf_as_tf32(Asm[(wm + lr + 8) * 136 + k0 + lc + 4]);
#pragma unroll
        for (int nt = 0; nt < 9; nt++) {
            uint32_t b0 = __float_as_uint(Bsm[(k0 + lc) * 72 + nt * 8 + lr]);
            uint32_t b1 = __float_as_uint(Bsm[(k0 + lc + 4) * 72 + nt * 8 + lr]);
            mma_tf32_16_8_8(c[nt], a, b0, b1);
        }
    }

    int src = lane & 28;
    float den1a = __shfl_sync(0xffffffffu, c[8][0], src);
    float den2a = __shfl_sync(0xffffffffu, c[8][1], src);
    float den1b = __shfl_sync(0xffffffffu, c[8][2], src);
    float den2b = __shfl_sync(0xffffffffu, c[8][3], src);
    float z1a = 1.f / (den1a + 1e-6f), z2a = 1.f / (den2a + 1e-6f);
    float z1b = 1.f / (den1b + 1e-6f), z2b = 1.f / (den2b + 1e-6f);

    int ra = b * Nn + m0 + wm + lr;
    int rb = ra + 8;
#pragma unroll
    for (int nt = 0; nt < 8; nt++) {
        int col = nt * 8 + 2 * lc;
        float za = (col < 32) ? z1a : z2a;
        float zb = (col < 32) ? z1b : z2b;
        int k = h * 64 + col;
        d_t[perm_idx(ra, k)]     = c[nt][0] * za;
        d_t[perm_idx(ra, k + 1)] = c[nt][1] * za;
        d_t[perm_idx(rb, k)]     = c[nt][2] * zb;
        d_t[perm_idx(rb, k + 1)] = c[nt][3] * zb;
    }
}

// =====================================================================
// depthwise conv + gate; d_t accessed via fragment indices, stores tf32
// =====================================================================
__global__ __launch_bounds__(512)
void conv_gate_kernel(const float* __restrict__ dwc_w,
                      const float* __restrict__ dwc_b)
{
    __shared__ float ws[64 * 25];
    __shared__ float bs[64];
    int y = blockIdx.x;
    int b = blockIdx.y;
    int c = threadIdx.x;
    int d = c & 63;
    for (int i = c; i < 64 * 25; i += 512) ws[i] = dwc_w[i];
    if (c < 64) bs[c] = dwc_b[c];
    __syncthreads();

    const float* vbase = &d_qgkv[(size_t)(b * Nn) * 2048 + 1536 + c];

    float win[5][5];
#pragma unroll
    for (int dy = 0; dy < 5; dy++) {
        int yy = y + dy - 2;
        bool yok = (unsigned)yy < HW;
#pragma unroll
        for (int j = 0; j < 5; j++) {
            int xx = j - 2;
            win[dy][j] = (yok && (unsigned)xx < HW)
                         ? vbase[(size_t)(yy * HW + xx) * 2048] : 0.f;
        }
    }

    for (int x = 0; x < HW; x++) {
        float acc = bs[d];
#pragma unroll
        for (int dy = 0; dy < 5; dy++)
#pragma unroll
            for (int j = 0; j < 5; j++)
                acc = fmaf(win[dy][j], ws[d * 25 + dy * 5 + j], acc);

        int i1 = b * Nn + y * HW + x;
        float g = d_qgkv[(size_t)i1 * 2048 + 512 + c];
        size_t pi = perm_idx(i1, c);
        d_t[pi] = to_tf32((d_t[pi] + acc) * g);

        int xx = x + 3;
        bool xok = xx < HW;
#pragma unroll
        for (int dy = 0; dy < 5; dy++) {
#pragma unroll
            for (int j = 0; j < 4; j++) win[dy][j] = win[dy][j + 1];
            int yy = y + dy - 2;
            win[dy][4] = (xok && (unsigned)yy < HW)
                         ? vbase[(size_t)(yy * HW + xx) * 2048] : 0.f;
        }
    }
}

// =====================================================================
// launch (launch #3 == big gemm for ncu capture)
// =====================================================================
extern "C" void kernel_launch(void* const* d_in, const int* in_sizes, int n_in,
                              void* d_out, int out_size)
{
    const float* x       = (const float*)d_in[0];
    const float* qg_w    = (const float*)d_in[1];
    const float* kv_w    = (const float*)d_in[2];
    const float* proj_w  = (const float*)d_in[3];
    const float* proj_b  = (const float*)d_in[4];
    const float* pos_enc = (const float*)d_in[5];
    const float* scale_p = (const float*)d_in[6];
    const float* power_p = (const float*)d_in[7];
    const float* dwc_w   = (const float*)d_in[8];
    const float* dwc_b   = (const float*)d_in[9];
    float* out = (float*)d_out;

    float *p_qgkv, *p_t, *p_wtc, *p_wt3, *p_xr;
    cudaGetSymbolAddress((void**)&p_qgkv, d_qgkv);
    cudaGetSymbolAddress((void**)&p_t,    d_t);
    cudaGetSymbolAddress((void**)&p_wtc,  d_wtc);
    cudaGetSymbolAddress((void**)&p_wt3,  d_wt3);
    cudaGetSymbolAddress((void**)&p_xr,   d_xr);

    cudaFuncSetAttribute(gemm_mma, cudaFuncAttributeMaxDynamicSharedMemorySize,
                         GEMM_SMEM);
    cudaFuncSetAttribute(attn_mma, cudaFuncAttributeMaxDynamicSharedMemorySize,
                         ATT_SMEM);

    dim3 tb(32, 8);
    prep_params<<<1, 512>>>(scale_p, power_p);                       // 0
    permute_x<<<Mrows * 128 / 256, 256>>>(x);                        // 1
    transpose_qgkv<<<dim3(64, 16), tb>>>(qg_w, kv_w);                // 2
    gemm_mma<<<dim3(8, Mrows / 128), 256, GEMM_SMEM>>>(              // 3 (profiled)
        p_xr, p_wtc, nullptr, p_qgkv, 2048);
    transpose_w<<<dim3(16, 16), tb>>>(proj_w, p_wt3, 512);           // 4
    zero_aux_kernel<<<1024, 256>>>();                                // 5
    features_kernel<<<Mrows / 16, 512>>>(pos_enc);                   // 6
    kvm_mma<<<dim3(Bn * NH, 2), 256>>>();                            // 7
    build_kvm2<<<Bn * NH, 256>>>();                                  // 8
    attn_mma<<<dim3(Nn / 64, Bn * NH), 128, ATT_SMEM>>>();           // 9
    conv_gate_kernel<<<dim3(HW, Bn), 512>>>(dwc_w, dwc_b);           // 10
    gemm_mma<<<dim3(2, Mrows / 128), 256, GEMM_SMEM>>>(              // 11
        p_t, p_wt3, proj_b, out, 512);
}